// round 2
// baseline (speedup 1.0000x reference)
#include <cuda_runtime.h>

#define NN 1024
#define DD 64
#define NE 16384
#define NP 8192
#define LNEPS 1e-5f

// ------------------------- scratch (device globals; no allocs) -------------
__device__ float    d_h[NN*DD];
__device__ float    d_hn[NN*DD];
__device__ float    d_aggr[NN*DD];
__device__ float    d_deg[NN];
__device__ unsigned d_bitmap[NN*NN/32];   // 128 KB edge-indicator bitmap
__device__ float    d_vecp[NN*DD];
__device__ float    d_vecq[NN*DD];
__device__ float    d_VP[NN*DD];          // vec_p @ g_W[65:129]
__device__ float    d_VQ[NN*DD];          // vec_q @ g_W[129:193]
__device__ float    d_G[2*NP*DD];         // G at (pos) and (pos swapped)

// ------------------------- init ---------------------------------------------
__global__ void k_zero() {
    int t  = blockIdx.x*blockDim.x + threadIdx.x;
    int st = gridDim.x*blockDim.x;
    for (int i=t; i<NN*NN/32; i+=st) d_bitmap[i] = 0u;
    for (int i=t; i<NN;       i+=st) d_deg[i]    = 0.f;
    for (int i=t; i<NN*DD;    i+=st) { d_vecp[i]=0.f; d_vecq[i]=0.f; }
}

__global__ void k_zero_aggr() {
    int t = blockIdx.x*blockDim.x + threadIdx.x;
    if (t < NN*DD) d_aggr[t] = 0.f;
}

// ------------------------- phase A: node-level ------------------------------
__global__ void k_embed(const int* __restrict__ x, const float* __restrict__ emb) {
    int t = blockIdx.x*blockDim.x + threadIdx.x;
    if (t < NN*DD) d_h[t] = emb[x[t>>6]*DD + (t&63)];
}

__global__ void k_degbm(const int* __restrict__ ei) {
    int e = blockIdx.x*blockDim.x + threadIdx.x;
    if (e < NE) {
        int s = ei[e], d = ei[NE+e];
        atomicAdd(&d_deg[d], 1.f);
        unsigned idx = (unsigned)s*NN + (unsigned)d;
        atomicOr(&d_bitmap[idx>>5], 1u << (idx & 31u));
    }
}

__global__ void k_scatter(const int* __restrict__ ei, int layer) {
    const float* hs = layer ? d_hn : d_h;
    int t = blockIdx.x*blockDim.x + threadIdx.x;
    if (t < NE*DD) {
        int e = t>>6, c = t&63;
        atomicAdd(&d_aggr[ei[NE+e]*DD + c], hs[ei[e]*DD + c]);
    }
}

__global__ void k_sage(const float* __restrict__ Wl, const float* __restrict__ bl,
                       const float* __restrict__ Wr, int layer) {
    __shared__ float s_in[DD], s_ag[DD], s_red[DD];
    int i = blockIdx.x, c = threadIdx.x;
    const float* hs = layer ? d_hn : d_h;
    float*       hd = layer ? d_h  : d_hn;
    float dg = fmaxf(d_deg[i], 1.f);
    s_in[c] = hs[i*DD+c];
    s_ag[c] = d_aggr[i*DD+c] / dg;
    __syncthreads();
    const float* wl = Wl + layer*DD*DD;
    const float* wr = Wr + layer*DD*DD;
    float acc = bl[layer*DD + c];
    #pragma unroll 8
    for (int k=0; k<DD; k++)
        acc = fmaf(s_ag[k], wl[k*DD+c], fmaf(s_in[k], wr[k*DD+c], acc));
    s_red[c] = acc;
    __syncthreads();
    float m = 0.f;
    #pragma unroll 8
    for (int k=0; k<DD; k++) m += s_red[k];
    m *= (1.f/DD);
    float v = 0.f;
    #pragma unroll 8
    for (int k=0; k<DD; k++) { float dd0 = s_red[k]-m; v = fmaf(dd0, dd0, v); }
    v *= (1.f/DD);
    hd[i*DD+c] = (acc - m) * rsqrtf(v + LNEPS);
}

// ------------------------- phase B: fused n^2 pair kernel -------------------
struct PairSmem {
    float  hiT[DD][DD+1];   // transposed+padded: conflict-free strided reads
    float  hjT[DD][DD+1];
    float4 hw[DD][DD/4];    // h_W rows 0..63 (broadcast float4 reads)
    float  hwe[DD];         // h_W row 64 (edge channel)
    float  hb[DD];
    float  vp[DD][DD];      // row-sum partials (per-warp exclusive rows)
    float  vq[DD][DD+1];    // col-sum partials (padded: conflict-free atomics)
};

__global__ void __launch_bounds__(256,2) k_pair(const float* __restrict__ hW,
                                                const float* __restrict__ hb) {
    extern __shared__ char smraw[];
    PairSmem* sm = reinterpret_cast<PairSmem*>(smraw);
    int t  = threadIdx.x;
    int i0 = blockIdx.y*64, j0 = blockIdx.x*64;

    #pragma unroll
    for (int r=0; r<16; r++) {
        int idx = t + r*256;
        int row = idx>>6, k = idx&63;
        sm->hiT[k][row] = d_h[(i0+row)*DD + k];
        sm->hjT[k][row] = d_h[(j0+row)*DD + k];
        reinterpret_cast<float*>(sm->hw)[idx] = hW[idx];   // rows 0..63
        reinterpret_cast<float*>(sm->vp)[idx] = 0.f;
    }
    for (int i=t; i<DD*(DD+1); i+=256) reinterpret_cast<float*>(sm->vq)[i] = 0.f;
    if (t < DD) { sm->hwe[t] = hW[DD*DD + t]; sm->hb[t] = hb[t]; }
    __syncthreads();

    int lane = t & 31, w = t >> 5;
    float acc[DD];

    for (int it=0; it<8; it++) {
        int ii = w*8 + it;                        // warp-exclusive i rows
        unsigned bmbase = (unsigned)(i0+ii)*NN + (unsigned)j0;
        for (int jt=0; jt<2; jt++) {
            int jj = lane + 32*jt;
            unsigned idx = bmbase + (unsigned)jj;
            float e = ((d_bitmap[idx>>5] >> (idx & 31u)) & 1u) ? 1.f : 0.f;

            #pragma unroll
            for (int c=0; c<DD; c++) acc[c] = fmaf(e, sm->hwe[c], sm->hb[c]);

            #pragma unroll 4
            for (int k=0; k<DD; k++) {
                float a = sm->hiT[k][ii] * sm->hjT[k][jj];
                #pragma unroll
                for (int c4=0; c4<16; c4++) {
                    float4 wv = sm->hw[k][c4];
                    acc[4*c4+0] = fmaf(a, wv.x, acc[4*c4+0]);
                    acc[4*c4+1] = fmaf(a, wv.y, acc[4*c4+1]);
                    acc[4*c4+2] = fmaf(a, wv.z, acc[4*c4+2]);
                    acc[4*c4+3] = fmaf(a, wv.w, acc[4*c4+3]);
                }
            }
            // LayerNorm over 64 channels (thread-local) + relu + reductions
            float m = 0.f;
            #pragma unroll
            for (int c=0; c<DD; c++) m += acc[c];
            m *= (1.f/DD);
            float v = 0.f;
            #pragma unroll
            for (int c=0; c<DD; c++) { float dd0 = acc[c]-m; v = fmaf(dd0, dd0, v); }
            float r = rsqrtf(v*(1.f/DD) + LNEPS);

            #pragma unroll
            for (int c=0; c<DD; c++) {
                float b = fmaxf((acc[c]-m)*r, 0.f);
                atomicAdd(&sm->vq[jj][c], b);               // conflict-free (pad 65)
                float bs = b;                                // vp: warp reduce over jj
                bs += __shfl_xor_sync(0xffffffffu, bs, 16);
                bs += __shfl_xor_sync(0xffffffffu, bs, 8);
                bs += __shfl_xor_sync(0xffffffffu, bs, 4);
                bs += __shfl_xor_sync(0xffffffffu, bs, 2);
                bs += __shfl_xor_sync(0xffffffffu, bs, 1);
                if (lane == 0) sm->vp[ii][c] += bs;          // warp-exclusive row
            }
        }
    }
    __syncthreads();
    #pragma unroll
    for (int r=0; r<16; r++) {
        int idx = t + r*256;
        int row = idx>>6, c = idx&63;
        atomicAdd(&d_vecp[(i0+row)*DD + c], sm->vp[row][c]);
        atomicAdd(&d_vecq[(j0+row)*DD + c], sm->vq[row][c]);
    }
}

// ------------------------- phase C: sampled G -------------------------------
__global__ void k_prec(const float* __restrict__ gW) {
    __shared__ float s_v[DD];
    int i = blockIdx.x, c = threadIdx.x;
    int which = blockIdx.y;
    const float* src = which ? d_vecq : d_vecp;
    const float* w   = gW + (which ? 129 : 65)*DD;
    float*       dst = which ? d_VQ : d_VP;
    s_v[c] = src[i*DD + c];
    __syncthreads();
    float acc = 0.f;
    #pragma unroll 8
    for (int k=0; k<DD; k++) acc = fmaf(s_v[k], w[k*DD+c], acc);
    dst[i*DD + c] = acc;
}

__global__ void k_gpairs(const int* __restrict__ pos, const float* __restrict__ gW,
                         const float* __restrict__ gb) {
    int gt = blockIdx.x*blockDim.x + threadIdx.x;
    int p = gt >> 5, lane = gt & 31;
    if (p >= 2*NP) return;
    int i, j;
    if (p < NP) { i = pos[2*p];         j = pos[2*p+1];      }
    else        { i = pos[2*(p-NP)+1];  j = pos[2*(p-NP)];   }
    int c0 = lane, c1 = lane + 32;
    const float* hi = d_h + i*DD;
    const float* hj = d_h + j*DD;
    float a0 = gb[c0] + d_VP[i*DD+c0] + d_VQ[j*DD+c0];
    float a1 = gb[c1] + d_VP[i*DD+c1] + d_VQ[j*DD+c1];
    unsigned bidx = (unsigned)i*NN + (unsigned)j;
    float e = ((d_bitmap[bidx>>5] >> (bidx & 31u)) & 1u) ? 1.f : 0.f;
    a0 = fmaf(e, gW[DD*DD + c0], a0);
    a1 = fmaf(e, gW[DD*DD + c1], a1);
    #pragma unroll 8
    for (int k=0; k<DD; k++) {
        float a = hi[k]*hj[k];
        a0 = fmaf(a, gW[k*DD + c0], a0);
        a1 = fmaf(a, gW[k*DD + c1], a1);
    }
    float s = a0 + a1;
    s += __shfl_xor_sync(0xffffffffu, s, 16);
    s += __shfl_xor_sync(0xffffffffu, s, 8);
    s += __shfl_xor_sync(0xffffffffu, s, 4);
    s += __shfl_xor_sync(0xffffffffu, s, 2);
    s += __shfl_xor_sync(0xffffffffu, s, 1);
    float m = s*(1.f/DD);
    float e0 = a0 - m, e1 = a1 - m;
    float vv = e0*e0 + e1*e1;
    vv += __shfl_xor_sync(0xffffffffu, vv, 16);
    vv += __shfl_xor_sync(0xffffffffu, vv, 8);
    vv += __shfl_xor_sync(0xffffffffu, vv, 4);
    vv += __shfl_xor_sync(0xffffffffu, vv, 2);
    vv += __shfl_xor_sync(0xffffffffu, vv, 1);
    float r = rsqrtf(vv*(1.f/DD) + LNEPS);
    d_G[p*DD + c0] = fmaxf(e0*r, 0.f);
    d_G[p*DD + c1] = fmaxf(e1*r, 0.f);
}

__global__ void k_out(const float* __restrict__ linW, const float* __restrict__ linb,
                      float* __restrict__ out) {
    int gt = blockIdx.x*blockDim.x + threadIdx.x;
    int p = gt >> 5, lane = gt & 31;
    if (p >= NP) return;
    float s = d_G[p*DD + lane]      * d_G[(p+NP)*DD + lane]      * linW[lane]
            + d_G[p*DD + lane + 32] * d_G[(p+NP)*DD + lane + 32] * linW[lane + 32];
    s += __shfl_xor_sync(0xffffffffu, s, 16);
    s += __shfl_xor_sync(0xffffffffu, s, 8);
    s += __shfl_xor_sync(0xffffffffu, s, 4);
    s += __shfl_xor_sync(0xffffffffu, s, 2);
    s += __shfl_xor_sync(0xffffffffu, s, 1);
    if (lane == 0) out[p] = s + linb[0];
}

// ------------------------- launch -------------------------------------------
extern "C" void kernel_launch(void* const* d_in, const int* in_sizes, int n_in,
                              void* d_out, int out_size) {
    const int*   x   = (const int*)d_in[0];
    const int*   ei  = (const int*)d_in[1];
    const int*   pos = (const int*)d_in[2];
    const float* emb = (const float*)d_in[3];
    const float* sWl = (const float*)d_in[4];
    const float* sbl = (const float*)d_in[5];
    const float* sWr = (const float*)d_in[6];
    const float* hW  = (const float*)d_in[7];
    const float* hb  = (const float*)d_in[8];
    const float* gW  = (const float*)d_in[9];
    const float* gb  = (const float*)d_in[10];
    const float* lW  = (const float*)d_in[11];
    const float* lb  = (const float*)d_in[12];
    float* out = (float*)d_out;

    cudaFuncSetAttribute(k_pair, cudaFuncAttributeMaxDynamicSharedMemorySize,
                         (int)sizeof(PairSmem));

    k_zero<<<64, 256>>>();
    k_embed<<<(NN*DD + 255)/256, 256>>>(x, emb);
    k_degbm<<<(NE + 255)/256, 256>>>(ei);
    for (int L=0; L<2; L++) {
        k_zero_aggr<<<NN*DD/256, 256>>>();
        k_scatter<<<NE*DD/256, 256>>>(ei, L);
        k_sage<<<NN, DD>>>(sWl, sbl, sWr, L);
    }
    k_pair<<<dim3(16,16), 256, sizeof(PairSmem)>>>(hW, hb);
    k_prec<<<dim3(NN,2), DD>>>(gW);
    k_gpairs<<<(2*NP*32)/256, 256>>>(pos, gW, gb);
    k_out<<<(NP*32)/256, 256>>>(lW, lb, out);
}

// round 3
// speedup vs baseline: 1.0291x; 1.0291x over previous
#include <cuda_runtime.h>

#define NN 1024
#define DD 64
#define NE 16384
#define NP 8192
#define LNEPS 1e-5f

typedef unsigned long long ull;

// ---------------- f32x2 packed helpers (sm_103a) ----------------------------
__device__ __forceinline__ ull pack2(float x, float y) {
    ull r; asm("mov.b64 %0, {%1,%2};" : "=l"(r) : "f"(x), "f"(y)); return r;
}
__device__ __forceinline__ void unpack2(ull v, float& x, float& y) {
    asm("mov.b64 {%0,%1}, %2;" : "=f"(x), "=f"(y) : "l"(v));
}
__device__ __forceinline__ ull add2(ull a, ull b) {
    ull r; asm("add.rn.f32x2 %0, %1, %2;" : "=l"(r) : "l"(a), "l"(b)); return r;
}
__device__ __forceinline__ ull mul2(ull a, ull b) {
    ull r; asm("mul.rn.f32x2 %0, %1, %2;" : "=l"(r) : "l"(a), "l"(b)); return r;
}
__device__ __forceinline__ void fma2(ull& d, ull a, ull b) {
    asm("fma.rn.f32x2 %0, %1, %2, %0;" : "+l"(d) : "l"(a), "l"(b));
}

// ------------------------- scratch (device globals) -------------------------
__device__ float    d_h[NN*DD];
__device__ float    d_hn[NN*DD];
__device__ float    d_aggr[NN*DD];
__device__ float    d_deg[NN];
__device__ unsigned d_bitmap[NN*NN/32];
__device__ float    d_vecp[NN*DD];
__device__ float    d_vecq[NN*DD];
__device__ float    d_VP[NN*DD];
__device__ float    d_VQ[NN*DD];
__device__ float    d_G[2*NP*DD];

// ------------------------- init ---------------------------------------------
__global__ void k_zero() {
    int t  = blockIdx.x*blockDim.x + threadIdx.x;
    int st = gridDim.x*blockDim.x;
    for (int i=t; i<NN*NN/32; i+=st) d_bitmap[i] = 0u;
    for (int i=t; i<NN;       i+=st) d_deg[i]    = 0.f;
    for (int i=t; i<NN*DD;    i+=st) { d_vecp[i]=0.f; d_vecq[i]=0.f; }
}

__global__ void k_zero_aggr() {
    int t = blockIdx.x*blockDim.x + threadIdx.x;
    if (t < NN*DD) d_aggr[t] = 0.f;
}

// ------------------------- phase A ------------------------------------------
__global__ void k_embed(const int* __restrict__ x, const float* __restrict__ emb) {
    int t = blockIdx.x*blockDim.x + threadIdx.x;
    if (t < NN*DD) d_h[t] = emb[x[t>>6]*DD + (t&63)];
}

__global__ void k_degbm(const int* __restrict__ ei) {
    int e = blockIdx.x*blockDim.x + threadIdx.x;
    if (e < NE) {
        int s = ei[e], d = ei[NE+e];
        atomicAdd(&d_deg[d], 1.f);
        unsigned idx = (unsigned)s*NN + (unsigned)d;
        atomicOr(&d_bitmap[idx>>5], 1u << (idx & 31u));
    }
}

__global__ void k_scatter(const int* __restrict__ ei, int layer) {
    const float* hs = layer ? d_hn : d_h;
    int t = blockIdx.x*blockDim.x + threadIdx.x;
    if (t < NE*DD) {
        int e = t>>6, c = t&63;
        atomicAdd(&d_aggr[ei[NE+e]*DD + c], hs[ei[e]*DD + c]);
    }
}

__global__ void k_sage(const float* __restrict__ Wl, const float* __restrict__ bl,
                       const float* __restrict__ Wr, int layer) {
    __shared__ float s_in[DD], s_ag[DD], s_red[DD];
    int i = blockIdx.x, c = threadIdx.x;
    const float* hs = layer ? d_hn : d_h;
    float*       hd = layer ? d_h  : d_hn;
    float dg = fmaxf(d_deg[i], 1.f);
    s_in[c] = hs[i*DD+c];
    s_ag[c] = d_aggr[i*DD+c] / dg;
    __syncthreads();
    const float* wl = Wl + layer*DD*DD;
    const float* wr = Wr + layer*DD*DD;
    float acc = bl[layer*DD + c];
    #pragma unroll 8
    for (int k=0; k<DD; k++)
        acc = fmaf(s_ag[k], wl[k*DD+c], fmaf(s_in[k], wr[k*DD+c], acc));
    s_red[c] = acc;
    __syncthreads();
    float m = 0.f;
    #pragma unroll 8
    for (int k=0; k<DD; k++) m += s_red[k];
    m *= (1.f/DD);
    float v = 0.f;
    #pragma unroll 8
    for (int k=0; k<DD; k++) { float dd0 = s_red[k]-m; v = fmaf(dd0, dd0, v); }
    v *= (1.f/DD);
    hd[i*DD+c] = (acc - m) * rsqrtf(v + LNEPS);
}

// ------------------------- phase B: fused n^2 pair kernel -------------------
struct PairSmem {
    ulonglong2 hw2[DD][16];   // h_W rows 0..63, packed: LDS.128 -> 2x f32x2 operands
    ull        hwe2[DD/2];    // h_W row 64 packed
    ull        hb2[DD/2];     // bias packed
    float      hiT[DD][DD+1]; // transposed + padded (conflict-free)
    float      hjT[DD][DD+1];
};

__global__ void __launch_bounds__(256,1) k_pair(const float* __restrict__ hW,
                                                const float* __restrict__ hb) {
    extern __shared__ char smraw[];
    PairSmem* sm = reinterpret_cast<PairSmem*>(smraw);
    int t  = threadIdx.x;
    int i0 = blockIdx.y*64, j0 = blockIdx.x*64;

    float* hwf = reinterpret_cast<float*>(sm->hw2);
    #pragma unroll
    for (int r=0; r<16; r++) {
        int idx = t + r*256;
        int row = idx>>6, k = idx&63;
        sm->hiT[k][row] = d_h[(i0+row)*DD + k];
        sm->hjT[k][row] = d_h[(j0+row)*DD + k];
        hwf[idx] = hW[idx];
    }
    if (t < DD) {
        reinterpret_cast<float*>(sm->hwe2)[t] = hW[DD*DD + t];
        reinterpret_cast<float*>(sm->hb2)[t]  = hb[t];
    }
    __syncthreads();

    int lane = t & 31, w = t >> 5;
    ull acc2[DD/2];
    float bq[DD];

    for (int jt=0; jt<2; jt++) {
        int jj = lane + 32*jt;
        #pragma unroll
        for (int c=0; c<DD; c++) bq[c] = 0.f;

        for (int it=0; it<8; it++) {
            int ii = w*8 + it;
            unsigned idx = (unsigned)(i0+ii)*NN + (unsigned)(j0+jj);
            float e = ((d_bitmap[idx>>5] >> (idx & 31u)) & 1u) ? 1.f : 0.f;
            ull e2 = pack2(e, e);

            #pragma unroll
            for (int q=0; q<DD/2; q++) {
                acc2[q] = sm->hb2[q];
                fma2(acc2[q], e2, sm->hwe2[q]);
            }

            #pragma unroll 4
            for (int k=0; k<DD; k++) {
                float a = sm->hiT[k][ii] * sm->hjT[k][jj];
                ull a2 = pack2(a, a);
                #pragma unroll
                for (int q=0; q<16; q++) {
                    ulonglong2 wv = sm->hw2[k][q];
                    fma2(acc2[2*q],   a2, wv.x);
                    fma2(acc2[2*q+1], a2, wv.y);
                }
            }

            // ---- LayerNorm (packed) ----
            ull s0=acc2[0], s1=acc2[1], s2=acc2[2], s3=acc2[3];
            #pragma unroll
            for (int q=4; q<32; q+=4) {
                s0 = add2(s0, acc2[q]);   s1 = add2(s1, acc2[q+1]);
                s2 = add2(s2, acc2[q+2]); s3 = add2(s3, acc2[q+3]);
            }
            float mx, my; unpack2(add2(add2(s0,s1), add2(s2,s3)), mx, my);
            float m = (mx + my) * (1.f/DD);
            ull nm2 = pack2(-m, -m);

            ull d0 = add2(acc2[0], nm2), v0 = mul2(d0, d0);
            ull d1 = add2(acc2[1], nm2), v1 = mul2(d1, d1);
            ull d2 = add2(acc2[2], nm2), v2 = mul2(d2, d2);
            ull d3 = add2(acc2[3], nm2), v3 = mul2(d3, d3);
            #pragma unroll
            for (int q=4; q<32; q+=4) {
                ull dd;
                dd = add2(acc2[q],   nm2); fma2(v0, dd, dd);
                dd = add2(acc2[q+1], nm2); fma2(v1, dd, dd);
                dd = add2(acc2[q+2], nm2); fma2(v2, dd, dd);
                dd = add2(acc2[q+3], nm2); fma2(v3, dd, dd);
            }
            float vx, vy; unpack2(add2(add2(v0,v1), add2(v2,v3)), vx, vy);
            float r = rsqrtf((vx + vy)*(1.f/DD) + LNEPS);

            // ---- relu + reductions: bq regs (vq), shuffle+lane0 RED (vp) ----
            float* vprow = &d_vecp[(i0+ii)*DD];
            #pragma unroll
            for (int q=0; q<32; q++) {
                float a0, a1; unpack2(add2(acc2[q], nm2), a0, a1);
                float b0 = fmaxf(a0*r, 0.f);
                float b1 = fmaxf(a1*r, 0.f);
                bq[2*q]   += b0;
                bq[2*q+1] += b1;
                float t0 = b0, t1 = b1;
                t0 += __shfl_xor_sync(0xffffffffu, t0, 16);
                t1 += __shfl_xor_sync(0xffffffffu, t1, 16);
                t0 += __shfl_xor_sync(0xffffffffu, t0, 8);
                t1 += __shfl_xor_sync(0xffffffffu, t1, 8);
                t0 += __shfl_xor_sync(0xffffffffu, t0, 4);
                t1 += __shfl_xor_sync(0xffffffffu, t1, 4);
                t0 += __shfl_xor_sync(0xffffffffu, t0, 2);
                t1 += __shfl_xor_sync(0xffffffffu, t1, 2);
                t0 += __shfl_xor_sync(0xffffffffu, t0, 1);
                t1 += __shfl_xor_sync(0xffffffffu, t1, 1);
                if (lane == 0) {
                    atomicAdd(&vprow[2*q],   t0);
                    atomicAdd(&vprow[2*q+1], t1);
                }
            }
        }

        // flush vq: one RED per channel per warp per jt (spread across lanes)
        float* vqrow = &d_vecq[(j0+jj)*DD];
        #pragma unroll
        for (int c=0; c<DD; c++) atomicAdd(&vqrow[c], bq[c]);
    }
}

// ------------------------- phase C ------------------------------------------
__global__ void k_prec(const float* __restrict__ gW) {
    __shared__ float s_v[DD];
    int i = blockIdx.x, c = threadIdx.x;
    int which = blockIdx.y;
    const float* src = which ? d_vecq : d_vecp;
    const float* w   = gW + (which ? 129 : 65)*DD;
    float*       dst = which ? d_VQ : d_VP;
    s_v[c] = src[i*DD + c];
    __syncthreads();
    float acc = 0.f;
    #pragma unroll 8
    for (int k=0; k<DD; k++) acc = fmaf(s_v[k], w[k*DD+c], acc);
    dst[i*DD + c] = acc;
}

__global__ void k_gpairs(const int* __restrict__ pos, const float* __restrict__ gW,
                         const float* __restrict__ gb) {
    int gt = blockIdx.x*blockDim.x + threadIdx.x;
    int p = gt >> 5, lane = gt & 31;
    if (p >= 2*NP) return;
    int i, j;
    if (p < NP) { i = pos[2*p];         j = pos[2*p+1];      }
    else        { i = pos[2*(p-NP)+1];  j = pos[2*(p-NP)];   }
    int c0 = lane, c1 = lane + 32;
    const float* hi = d_h + i*DD;
    const float* hj = d_h + j*DD;
    float a0 = gb[c0] + d_VP[i*DD+c0] + d_VQ[j*DD+c0];
    float a1 = gb[c1] + d_VP[i*DD+c1] + d_VQ[j*DD+c1];
    unsigned bidx = (unsigned)i*NN + (unsigned)j;
    float e = ((d_bitmap[bidx>>5] >> (bidx & 31u)) & 1u) ? 1.f : 0.f;
    a0 = fmaf(e, gW[DD*DD + c0], a0);
    a1 = fmaf(e, gW[DD*DD + c1], a1);
    #pragma unroll 8
    for (int k=0; k<DD; k++) {
        float a = hi[k]*hj[k];
        a0 = fmaf(a, gW[k*DD + c0], a0);
        a1 = fmaf(a, gW[k*DD + c1], a1);
    }
    float s = a0 + a1;
    s += __shfl_xor_sync(0xffffffffu, s, 16);
    s += __shfl_xor_sync(0xffffffffu, s, 8);
    s += __shfl_xor_sync(0xffffffffu, s, 4);
    s += __shfl_xor_sync(0xffffffffu, s, 2);
    s += __shfl_xor_sync(0xffffffffu, s, 1);
    float m = s*(1.f/DD);
    float e0 = a0 - m, e1 = a1 - m;
    float vv = e0*e0 + e1*e1;
    vv += __shfl_xor_sync(0xffffffffu, vv, 16);
    vv += __shfl_xor_sync(0xffffffffu, vv, 8);
    vv += __shfl_xor_sync(0xffffffffu, vv, 4);
    vv += __shfl_xor_sync(0xffffffffu, vv, 2);
    vv += __shfl_xor_sync(0xffffffffu, vv, 1);
    float r = rsqrtf(vv*(1.f/DD) + LNEPS);
    d_G[p*DD + c0] = fmaxf(e0*r, 0.f);
    d_G[p*DD + c1] = fmaxf(e1*r, 0.f);
}

__global__ void k_out(const float* __restrict__ linW, const float* __restrict__ linb,
                      float* __restrict__ out) {
    int gt = blockIdx.x*blockDim.x + threadIdx.x;
    int p = gt >> 5, lane = gt & 31;
    if (p >= NP) return;
    float s = d_G[p*DD + lane]      * d_G[(p+NP)*DD + lane]      * linW[lane]
            + d_G[p*DD + lane + 32] * d_G[(p+NP)*DD + lane + 32] * linW[lane + 32];
    s += __shfl_xor_sync(0xffffffffu, s, 16);
    s += __shfl_xor_sync(0xffffffffu, s, 8);
    s += __shfl_xor_sync(0xffffffffu, s, 4);
    s += __shfl_xor_sync(0xffffffffu, s, 2);
    s += __shfl_xor_sync(0xffffffffu, s, 1);
    if (lane == 0) out[p] = s + linb[0];
}

// ------------------------- launch -------------------------------------------
extern "C" void kernel_launch(void* const* d_in, const int* in_sizes, int n_in,
                              void* d_out, int out_size) {
    const int*   x   = (const int*)d_in[0];
    const int*   ei  = (const int*)d_in[1];
    const int*   pos = (const int*)d_in[2];
    const float* emb = (const float*)d_in[3];
    const float* sWl = (const float*)d_in[4];
    const float* sbl = (const float*)d_in[5];
    const float* sWr = (const float*)d_in[6];
    const float* hW  = (const float*)d_in[7];
    const float* hb  = (const float*)d_in[8];
    const float* gW  = (const float*)d_in[9];
    const float* gb  = (const float*)d_in[10];
    const float* lW  = (const float*)d_in[11];
    const float* lb  = (const float*)d_in[12];
    float* out = (float*)d_out;

    cudaFuncSetAttribute(k_pair, cudaFuncAttributeMaxDynamicSharedMemorySize,
                         (int)sizeof(PairSmem));

    k_zero<<<64, 256>>>();
    k_embed<<<(NN*DD + 255)/256, 256>>>(x, emb);
    k_degbm<<<(NE + 255)/256, 256>>>(ei);
    for (int L=0; L<2; L++) {
        k_zero_aggr<<<NN*DD/256, 256>>>();
        k_scatter<<<NE*DD/256, 256>>>(ei, L);
        k_sage<<<NN, DD>>>(sWl, sbl, sWr, L);
    }
    k_pair<<<dim3(16,16), 256, sizeof(PairSmem)>>>(hW, hb);
    k_prec<<<dim3(NN,2), DD>>>(gW);
    k_gpairs<<<(2*NP*32)/256, 256>>>(pos, gW, gb);
    k_out<<<(NP*32)/256, 256>>>(lW, lb, out);
}

// round 4
// speedup vs baseline: 2.1443x; 2.0837x over previous
#include <cuda_runtime.h>

#define NN 1024
#define DD 64
#define NE 16384
#define NP 8192
#define LNEPS 1e-5f

typedef unsigned long long ull;

// ---------------- f32x2 packed helpers (sm_103a) ----------------------------
__device__ __forceinline__ ull pack2(float x, float y) {
    ull r; asm("mov.b64 %0, {%1,%2};" : "=l"(r) : "f"(x), "f"(y)); return r;
}
__device__ __forceinline__ void unpack2(ull v, float& x, float& y) {
    asm("mov.b64 {%0,%1}, %2;" : "=f"(x), "=f"(y) : "l"(v));
}
__device__ __forceinline__ ull add2(ull a, ull b) {
    ull r; asm("add.rn.f32x2 %0, %1, %2;" : "=l"(r) : "l"(a), "l"(b)); return r;
}
__device__ __forceinline__ ull mul2(ull a, ull b) {
    ull r; asm("mul.rn.f32x2 %0, %1, %2;" : "=l"(r) : "l"(a), "l"(b)); return r;
}
__device__ __forceinline__ void fma2(ull& d, ull a, ull b) {
    asm("fma.rn.f32x2 %0, %1, %2, %0;" : "+l"(d) : "l"(a), "l"(b));
}

// ------------------------- scratch (device globals) -------------------------
__device__ float    d_h[NN*DD];
__device__ float    d_hn[NN*DD];
__device__ float    d_aggr[NN*DD];
__device__ float    d_deg[NN];
__device__ unsigned d_bitmap[NN*NN/32];
__device__ float    d_vecp[NN*DD];
__device__ float    d_vecq[NN*DD];
__device__ float    d_VP[NN*DD];
__device__ float    d_VQ[NN*DD];
__device__ float    d_G[2*NP*DD];

// ------------------------- init ---------------------------------------------
__global__ void k_zero() {
    int t  = blockIdx.x*blockDim.x + threadIdx.x;
    int st = gridDim.x*blockDim.x;
    for (int i=t; i<NN*NN/32; i+=st) d_bitmap[i] = 0u;
    for (int i=t; i<NN;       i+=st) d_deg[i]    = 0.f;
    for (int i=t; i<NN*DD;    i+=st) { d_vecp[i]=0.f; d_vecq[i]=0.f; }
}

__global__ void k_zero_aggr() {
    int t = blockIdx.x*blockDim.x + threadIdx.x;
    if (t < NN*DD) d_aggr[t] = 0.f;
}

// ------------------------- phase A ------------------------------------------
__global__ void k_embed(const int* __restrict__ x, const float* __restrict__ emb) {
    int t = blockIdx.x*blockDim.x + threadIdx.x;
    if (t < NN*DD) d_h[t] = emb[x[t>>6]*DD + (t&63)];
}

__global__ void k_degbm(const int* __restrict__ ei) {
    int e = blockIdx.x*blockDim.x + threadIdx.x;
    if (e < NE) {
        int s = ei[e], d = ei[NE+e];
        atomicAdd(&d_deg[d], 1.f);
        unsigned idx = (unsigned)s*NN + (unsigned)d;
        atomicOr(&d_bitmap[idx>>5], 1u << (idx & 31u));
    }
}

__global__ void k_scatter(const int* __restrict__ ei, int layer) {
    const float* hs = layer ? d_hn : d_h;
    int t = blockIdx.x*blockDim.x + threadIdx.x;
    if (t < NE*DD) {
        int e = t>>6, c = t&63;
        atomicAdd(&d_aggr[ei[NE+e]*DD + c], hs[ei[e]*DD + c]);
    }
}

__global__ void k_sage(const float* __restrict__ Wl, const float* __restrict__ bl,
                       const float* __restrict__ Wr, int layer) {
    __shared__ float s_in[DD], s_ag[DD], s_red[DD];
    int i = blockIdx.x, c = threadIdx.x;
    const float* hs = layer ? d_hn : d_h;
    float*       hd = layer ? d_h  : d_hn;
    float dg = fmaxf(d_deg[i], 1.f);
    s_in[c] = hs[i*DD+c];
    s_ag[c] = d_aggr[i*DD+c] / dg;
    __syncthreads();
    const float* wl = Wl + layer*DD*DD;
    const float* wr = Wr + layer*DD*DD;
    float acc = bl[layer*DD + c];
    #pragma unroll 8
    for (int k=0; k<DD; k++)
        acc = fmaf(s_ag[k], wl[k*DD+c], fmaf(s_in[k], wr[k*DD+c], acc));
    s_red[c] = acc;
    __syncthreads();
    float m = 0.f;
    #pragma unroll 8
    for (int k=0; k<DD; k++) m += s_red[k];
    m *= (1.f/DD);
    float v = 0.f;
    #pragma unroll 8
    for (int k=0; k<DD; k++) { float dd0 = s_red[k]-m; v = fmaf(dd0, dd0, v); }
    v *= (1.f/DD);
    hd[i*DD+c] = (acc - m) * rsqrtf(v + LNEPS);
}

// ------------------------- phase B: symmetric fused pair kernel -------------
struct PairSmem {
    ulonglong2 hw2[DD][16];      // h_W rows 0..63, packed for f32x2
    ull        hwe2[DD/2];       // h_W row 64 (edge channel)
    ull        hb2[DD/2];        // bias
    float      hiT[DD][DD+1];    // transposed + padded
    float      hjT[DD][DD+1];
    float      bt[8][32][DD+1];  // per-warp B-tile (colsum staging / bq staging)
    float      bp[8][32][DD+1];  // per-warp vp[j-row] accumulator (mirror emit)
    float      svp[DD][DD+1];    // block i-row vp accumulator (warp/lane exclusive)
    float      svq[DD][DD+1];    // block i-row vq accumulator (mirror emit)
};

__device__ __forceinline__ void ln_stats(const ull* acc2, float& m, float& rr) {
    ull s0=acc2[0], s1=acc2[1], s2=acc2[2], s3=acc2[3];
    #pragma unroll
    for (int q=4; q<32; q+=4) {
        s0 = add2(s0, acc2[q]);   s1 = add2(s1, acc2[q+1]);
        s2 = add2(s2, acc2[q+2]); s3 = add2(s3, acc2[q+3]);
    }
    float mx, my; unpack2(add2(add2(s0,s1), add2(s2,s3)), mx, my);
    m = (mx + my) * (1.f/DD);
    ull nm = pack2(-m, -m);
    ull dd, v0, v1, v2, v3;
    dd = add2(acc2[0], nm); v0 = mul2(dd, dd);
    dd = add2(acc2[1], nm); v1 = mul2(dd, dd);
    dd = add2(acc2[2], nm); v2 = mul2(dd, dd);
    dd = add2(acc2[3], nm); v3 = mul2(dd, dd);
    #pragma unroll
    for (int q=4; q<32; q+=4) {
        dd = add2(acc2[q],   nm); fma2(v0, dd, dd);
        dd = add2(acc2[q+1], nm); fma2(v1, dd, dd);
        dd = add2(acc2[q+2], nm); fma2(v2, dd, dd);
        dd = add2(acc2[q+3], nm); fma2(v3, dd, dd);
    }
    float vx, vy; unpack2(add2(add2(v0,v1), add2(v2,v3)), vx, vy);
    rr = rsqrtf((vx + vy)*(1.f/DD) + LNEPS);
}

__global__ void __launch_bounds__(256,1) k_pair(const float* __restrict__ hW,
                                                const float* __restrict__ hb) {
    extern __shared__ char smraw[];
    PairSmem* sm = reinterpret_cast<PairSmem*>(smraw);
    int t = threadIdx.x;

    // triangular tile decode: 136 blocks, bi <= bj
    int bi = 0, rem = blockIdx.x;
    while (rem >= 16 - bi) { rem -= 16 - bi; bi++; }
    int bj = bi + rem;
    int i0 = bi*64, j0 = bj*64;
    bool diag = (bi == bj);

    float* hwf = reinterpret_cast<float*>(sm->hw2);
    #pragma unroll
    for (int r=0; r<16; r++) {
        int idx = t + r*256;
        int row = idx>>6, k = idx&63;
        sm->hiT[k][row] = d_h[(i0+row)*DD + k];
        sm->hjT[k][row] = d_h[(j0+row)*DD + k];
        hwf[idx] = hW[idx];
        sm->svp[row][k] = 0.f;
        sm->svq[row][k] = 0.f;
    }
    if (t < DD) {
        reinterpret_cast<float*>(sm->hwe2)[t] = hW[DD*DD + t];
        reinterpret_cast<float*>(sm->hb2)[t]  = hb[t];
    }
    __syncthreads();

    int lane = t & 31, w = t >> 5;
    float (*bt)[DD+1]  = sm->bt[w];
    float (*bps)[DD+1] = sm->bp[w];
    ull acc2[32];
    float bq[DD];

    for (int jt=0; jt<2; jt++) {
        int jj = lane + 32*jt;
        #pragma unroll
        for (int c=0; c<DD; c++) bq[c] = 0.f;
        if (!diag) {
            #pragma unroll
            for (int c=0; c<DD; c++) bps[lane][c] = 0.f;
        }

        for (int it=0; it<8; it++) {
            int ii = w*8 + it;
            // ---- symmetric base GEMM (packed f32x2) ----
            #pragma unroll
            for (int q=0; q<32; q++) acc2[q] = sm->hb2[q];
            #pragma unroll 2
            for (int k=0; k<DD; k++) {
                float a = sm->hiT[k][ii] * sm->hjT[k][jj];
                ull a2 = pack2(a, a);
                #pragma unroll
                for (int q=0; q<16; q++) {
                    ulonglong2 wv = sm->hw2[k][q];
                    fma2(acc2[2*q],   a2, wv.x);
                    fma2(acc2[2*q+1], a2, wv.y);
                }
            }
            unsigned gi = (unsigned)(i0+ii), gj = (unsigned)(j0+jj);
            unsigned idx1 = gi*NN + gj;
            float e1 = ((d_bitmap[idx1>>5] >> (idx1 & 31u)) & 1u) ? 1.f : 0.f;
            ull e1p = pack2(e1, e1);
            #pragma unroll
            for (int q=0; q<32; q++) fma2(acc2[q], e1p, sm->hwe2[q]);

            // ---- LN + relu, emit (i,j): vq[jj] in regs, vp[ii] via colsum ----
            float m, rr; ln_stats(acc2, m, rr);
            #pragma unroll
            for (int q=0; q<32; q++) {
                float a0, a1; unpack2(acc2[q], a0, a1);
                float b0 = fmaxf((a0 - m)*rr, 0.f);
                float b1 = fmaxf((a1 - m)*rr, 0.f);
                bq[2*q]   += b0;  bq[2*q+1] += b1;
                bt[lane][2*q] = b0;  bt[lane][2*q+1] = b1;
            }
            __syncwarp();
            {
                float s0 = 0.f, s1 = 0.f;
                #pragma unroll
                for (int r=0; r<32; r++) { s0 += bt[r][lane]; s1 += bt[r][lane+32]; }
                sm->svp[ii][lane]    += s0;    // warp/lane-exclusive slot
                sm->svp[ii][lane+32] += s1;
            }

            if (!diag) {
                __syncwarp();
                // ---- mirror emit (j,i): acc' = acc + (e2-e1)*hwe ----
                unsigned idx2 = gj*NN + gi;
                float e2 = ((d_bitmap[idx2>>5] >> (idx2 & 31u)) & 1u) ? 1.f : 0.f;
                ull dep = pack2(e2 - e1, e2 - e1);
                #pragma unroll
                for (int q=0; q<32; q++) fma2(acc2[q], dep, sm->hwe2[q]);
                float m2, rr2; ln_stats(acc2, m2, rr2);
                #pragma unroll
                for (int q=0; q<32; q++) {
                    float a0, a1; unpack2(acc2[q], a0, a1);
                    float b0 = fmaxf((a0 - m2)*rr2, 0.f);
                    float b1 = fmaxf((a1 - m2)*rr2, 0.f);
                    bps[lane][2*q]   += b0;  bps[lane][2*q+1] += b1;  // vp[jj]
                    bt[lane][2*q] = b0;  bt[lane][2*q+1] = b1;
                }
                __syncwarp();
                float s0 = 0.f, s1 = 0.f;
                #pragma unroll
                for (int r=0; r<32; r++) { s0 += bt[r][lane]; s1 += bt[r][lane+32]; }
                sm->svq[ii][lane]    += s0;   // vq[ii] from mirror
                sm->svq[ii][lane+32] += s1;
                __syncwarp();
            } else {
                __syncwarp();
            }
        }

        // ---- block-reduce bq (vq[j0+jj]) through bt, single REDG per entry ----
        #pragma unroll
        for (int c=0; c<DD; c++) bt[lane][c] = bq[c];
        __syncthreads();
        for (int idx=t; idx<32*DD; idx+=256) {
            int r = idx>>6, c = idx&63;
            float s = 0.f;
            #pragma unroll
            for (int ww=0; ww<8; ww++) s += sm->bt[ww][r][c];
            atomicAdd(&d_vecq[(j0 + 32*jt + r)*DD + c], s);
        }
        if (!diag) {
            __syncthreads();
            for (int idx=t; idx<32*DD; idx+=256) {
                int r = idx>>6, c = idx&63;
                float s = 0.f;
                #pragma unroll
                for (int ww=0; ww<8; ww++) s += sm->bp[ww][r][c];
                atomicAdd(&d_vecp[(j0 + 32*jt + r)*DD + c], s);
            }
        }
        __syncthreads();
    }

    // ---- flush block i-row accumulators ----
    for (int idx=t; idx<DD*DD; idx+=256) {
        int ii = idx>>6, c = idx&63;
        atomicAdd(&d_vecp[(i0+ii)*DD + c], sm->svp[ii][c]);
        if (!diag) atomicAdd(&d_vecq[(i0+ii)*DD + c], sm->svq[ii][c]);
    }
}

// ------------------------- phase C ------------------------------------------
__global__ void k_prec(const float* __restrict__ gW) {
    __shared__ float s_v[DD];
    int i = blockIdx.x, c = threadIdx.x;
    int which = blockIdx.y;
    const float* src = which ? d_vecq : d_vecp;
    const float* w   = gW + (which ? 129 : 65)*DD;
    float*       dst = which ? d_VQ : d_VP;
    s_v[c] = src[i*DD + c];
    __syncthreads();
    float acc = 0.f;
    #pragma unroll 8
    for (int k=0; k<DD; k++) acc = fmaf(s_v[k], w[k*DD+c], acc);
    dst[i*DD + c] = acc;
}

__global__ void k_gpairs(const int* __restrict__ pos, const float* __restrict__ gW,
                         const float* __restrict__ gb) {
    int gt = blockIdx.x*blockDim.x + threadIdx.x;
    int p = gt >> 5, lane = gt & 31;
    if (p >= 2*NP) return;
    int i, j;
    if (p < NP) { i = pos[2*p];         j = pos[2*p+1];      }
    else        { i = pos[2*(p-NP)+1];  j = pos[2*(p-NP)];   }
    int c0 = lane, c1 = lane + 32;
    const float* hi = d_h + i*DD;
    const float* hj = d_h + j*DD;
    float a0 = gb[c0] + d_VP[i*DD+c0] + d_VQ[j*DD+c0];
    float a1 = gb[c1] + d_VP[i*DD+c1] + d_VQ[j*DD+c1];
    unsigned bidx = (unsigned)i*NN + (unsigned)j;
    float e = ((d_bitmap[bidx>>5] >> (bidx & 31u)) & 1u) ? 1.f : 0.f;
    a0 = fmaf(e, gW[DD*DD + c0], a0);
    a1 = fmaf(e, gW[DD*DD + c1], a1);
    #pragma unroll 8
    for (int k=0; k<DD; k++) {
        float a = hi[k]*hj[k];
        a0 = fmaf(a, gW[k*DD + c0], a0);
        a1 = fmaf(a, gW[k*DD + c1], a1);
    }
    float s = a0 + a1;
    s += __shfl_xor_sync(0xffffffffu, s, 16);
    s += __shfl_xor_sync(0xffffffffu, s, 8);
    s += __shfl_xor_sync(0xffffffffu, s, 4);
    s += __shfl_xor_sync(0xffffffffu, s, 2);
    s += __shfl_xor_sync(0xffffffffu, s, 1);
    float m = s*(1.f/DD);
    float e0 = a0 - m, e1 = a1 - m;
    float vv = e0*e0 + e1*e1;
    vv += __shfl_xor_sync(0xffffffffu, vv, 16);
    vv += __shfl_xor_sync(0xffffffffu, vv, 8);
    vv += __shfl_xor_sync(0xffffffffu, vv, 4);
    vv += __shfl_xor_sync(0xffffffffu, vv, 2);
    vv += __shfl_xor_sync(0xffffffffu, vv, 1);
    float r = rsqrtf(vv*(1.f/DD) + LNEPS);
    d_G[p*DD + c0] = fmaxf(e0*r, 0.f);
    d_G[p*DD + c1] = fmaxf(e1*r, 0.f);
}

__global__ void k_out(const float* __restrict__ linW, const float* __restrict__ linb,
                      float* __restrict__ out) {
    int gt = blockIdx.x*blockDim.x + threadIdx.x;
    int p = gt >> 5, lane = gt & 31;
    if (p >= NP) return;
    float s = d_G[p*DD + lane]      * d_G[(p+NP)*DD + lane]      * linW[lane]
            + d_G[p*DD + lane + 32] * d_G[(p+NP)*DD + lane + 32] * linW[lane + 32];
    s += __shfl_xor_sync(0xffffffffu, s, 16);
    s += __shfl_xor_sync(0xffffffffu, s, 8);
    s += __shfl_xor_sync(0xffffffffu, s, 4);
    s += __shfl_xor_sync(0xffffffffu, s, 2);
    s += __shfl_xor_sync(0xffffffffu, s, 1);
    if (lane == 0) out[p] = s + linb[0];
}

// ------------------------- launch -------------------------------------------
extern "C" void kernel_launch(void* const* d_in, const int* in_sizes, int n_in,
                              void* d_out, int out_size) {
    const int*   x   = (const int*)d_in[0];
    const int*   ei  = (const int*)d_in[1];
    const int*   pos = (const int*)d_in[2];
    const float* emb = (const float*)d_in[3];
    const float* sWl = (const float*)d_in[4];
    const float* sbl = (const float*)d_in[5];
    const float* sWr = (const float*)d_in[6];
    const float* hW  = (const float*)d_in[7];
    const float* hb  = (const float*)d_in[8];
    const float* gW  = (const float*)d_in[9];
    const float* gb  = (const float*)d_in[10];
    const float* lW  = (const float*)d_in[11];
    const float* lb  = (const float*)d_in[12];
    float* out = (float*)d_out;

    cudaFuncSetAttribute(k_pair, cudaFuncAttributeMaxDynamicSharedMemorySize,
                         (int)sizeof(PairSmem));

    k_zero<<<64, 256>>>();
    k_embed<<<(NN*DD + 255)/256, 256>>>(x, emb);
    k_degbm<<<(NE + 255)/256, 256>>>(ei);
    for (int L=0; L<2; L++) {
        k_zero_aggr<<<NN*DD/256, 256>>>();
        k_scatter<<<NE*DD/256, 256>>>(ei, L);
        k_sage<<<NN, DD>>>(sWl, sbl, sWr, L);
    }
    k_pair<<<136, 256, sizeof(PairSmem)>>>(hW, hb);
    k_prec<<<dim3(NN,2), DD>>>(gW);
    k_gpairs<<<(2*NP*32)/256, 256>>>(pos, gW, gb);
    k_out<<<(NP*32)/256, 256>>>(lW, lb, out);
}

// round 5
// speedup vs baseline: 2.6341x; 1.2284x over previous
#include <cuda_runtime.h>

#define NN 1024
#define DD 64
#define NE 16384
#define NP 8192
#define LNEPS 1e-5f

typedef unsigned long long ull;

// ---------------- f32x2 packed helpers (sm_103a) ----------------------------
__device__ __forceinline__ ull pack2(float x, float y) {
    ull r; asm("mov.b64 %0, {%1,%2};" : "=l"(r) : "f"(x), "f"(y)); return r;
}
__device__ __forceinline__ void unpack2(ull v, float& x, float& y) {
    asm("mov.b64 {%0,%1}, %2;" : "=f"(x), "=f"(y) : "l"(v));
}
__device__ __forceinline__ ull add2(ull a, ull b) {
    ull r; asm("add.rn.f32x2 %0, %1, %2;" : "=l"(r) : "l"(a), "l"(b)); return r;
}
__device__ __forceinline__ ull mul2(ull a, ull b) {
    ull r; asm("mul.rn.f32x2 %0, %1, %2;" : "=l"(r) : "l"(a), "l"(b)); return r;
}
__device__ __forceinline__ void fma2(ull& d, ull a, ull b) {
    asm("fma.rn.f32x2 %0, %1, %2, %0;" : "+l"(d) : "l"(a), "l"(b));
}

// ------------------------- scratch (device globals) -------------------------
__device__ float    d_h[NN*DD];
__device__ float    d_hn[NN*DD];
__device__ float    d_aggr[NN*DD];
__device__ float    d_deg[NN];
__device__ unsigned d_bitmap[NN*NN/32];
__device__ float    d_vecp[NN*DD];
__device__ float    d_vecq[NN*DD];
__device__ float    d_VP[NN*DD];
__device__ float    d_VQ[NN*DD];
__device__ float    d_G[2*NP*DD];

// ------------------------- phase A ------------------------------------------
__global__ void k_init(const int* __restrict__ x, const float* __restrict__ emb) {
    int t  = blockIdx.x*blockDim.x + threadIdx.x;
    int st = gridDim.x*blockDim.x;
    for (int i=t; i<NN*NN/32; i+=st) d_bitmap[i] = 0u;
    for (int i=t; i<NN;       i+=st) d_deg[i]    = 0.f;
    for (int i=t; i<NN*DD;    i+=st) {
        d_vecp[i]=0.f; d_vecq[i]=0.f; d_aggr[i]=0.f;
        d_h[i] = emb[x[i>>6]*DD + (i&63)];
    }
}

// layer-0 scatter fused with degree + bitmap build
__global__ void k_scat0(const int* __restrict__ ei) {
    int t = blockIdx.x*blockDim.x + threadIdx.x;
    if (t < NE*DD) {
        int e = t>>6, c = t&63;
        int s = ei[e], d = ei[NE+e];
        atomicAdd(&d_aggr[d*DD + c], d_h[s*DD + c]);
        if (c == 0) {
            atomicAdd(&d_deg[d], 1.f);
            unsigned idx = (unsigned)s*NN + (unsigned)d;
            atomicOr(&d_bitmap[idx>>5], 1u << (idx & 31u));
        }
    }
}

__global__ void k_scatter(const int* __restrict__ ei) {
    int t = blockIdx.x*blockDim.x + threadIdx.x;
    if (t < NE*DD) {
        int e = t>>6, c = t&63;
        atomicAdd(&d_aggr[ei[NE+e]*DD + c], d_hn[ei[e]*DD + c]);
    }
}

__global__ void k_sage(const float* __restrict__ Wl, const float* __restrict__ bl,
                       const float* __restrict__ Wr, int layer) {
    __shared__ float s_in[DD], s_ag[DD], s_red[DD];
    int i = blockIdx.x, c = threadIdx.x;
    const float* hs = layer ? d_hn : d_h;
    float*       hd = layer ? d_h  : d_hn;
    float dg = fmaxf(d_deg[i], 1.f);
    s_in[c] = hs[i*DD+c];
    s_ag[c] = d_aggr[i*DD+c] / dg;
    d_aggr[i*DD+c] = 0.f;            // reset for next layer's scatter
    __syncthreads();
    const float* wl = Wl + layer*DD*DD;
    const float* wr = Wr + layer*DD*DD;
    float acc = bl[layer*DD + c];
    #pragma unroll 8
    for (int k=0; k<DD; k++)
        acc = fmaf(s_ag[k], wl[k*DD+c], fmaf(s_in[k], wr[k*DD+c], acc));
    s_red[c] = acc;
    __syncthreads();
    float m = 0.f;
    #pragma unroll 8
    for (int k=0; k<DD; k++) m += s_red[k];
    m *= (1.f/DD);
    float v = 0.f;
    #pragma unroll 8
    for (int k=0; k<DD; k++) { float dd0 = s_red[k]-m; v = fmaf(dd0, dd0, v); }
    v *= (1.f/DD);
    hd[i*DD+c] = (acc - m) * rsqrtf(v + LNEPS);
}

// ------------------------- phase B: symmetric fused pair kernel -------------
struct PairSmem {
    ulonglong2 hw2[DD][16];      // 16384 B : h_W rows 0..63 packed
    ull        hwe2[DD/2];       //   256 B : h_W row 64 (edge)
    ull        hb2[DD/2];        //   256 B : bias
    float      hiT[DD][DD+1];    // 16640 B
    float      hjT[DD][DD+1];    // 16640 B
    ull        bt[8][32][33];    // 67584 B : per-warp B-tile staging (packed)
    ull        bpa[8][32][33];   // 67584 B : per-warp mirror vp accumulator
    ull        svp2[DD][33];     // 16896 B : block i-row vp accumulator
    ull        svq2[DD][33];     // 16896 B : block i-row vq accumulator (mirror)
    unsigned   bm0[DD][2];       //   512 B : bitmap slab rows i0.., cols j0..
    unsigned   bm1[DD][2];       //   512 B : bitmap slab rows j0.., cols i0..
};

__device__ __forceinline__ void ln_stats(const ull* acc2, float& m, float& rr) {
    ull s0=acc2[0], s1=acc2[1], s2=acc2[2], s3=acc2[3];
    #pragma unroll
    for (int q=4; q<32; q+=4) {
        s0 = add2(s0, acc2[q]);   s1 = add2(s1, acc2[q+1]);
        s2 = add2(s2, acc2[q+2]); s3 = add2(s3, acc2[q+3]);
    }
    float mx, my; unpack2(add2(add2(s0,s1), add2(s2,s3)), mx, my);
    m = (mx + my) * (1.f/DD);
    ull nm = pack2(-m, -m);
    ull dd, v0, v1, v2, v3;
    dd = add2(acc2[0], nm); v0 = mul2(dd, dd);
    dd = add2(acc2[1], nm); v1 = mul2(dd, dd);
    dd = add2(acc2[2], nm); v2 = mul2(dd, dd);
    dd = add2(acc2[3], nm); v3 = mul2(dd, dd);
    #pragma unroll
    for (int q=4; q<32; q+=4) {
        dd = add2(acc2[q],   nm); fma2(v0, dd, dd);
        dd = add2(acc2[q+1], nm); fma2(v1, dd, dd);
        dd = add2(acc2[q+2], nm); fma2(v2, dd, dd);
        dd = add2(acc2[q+3], nm); fma2(v3, dd, dd);
    }
    float vx, vy; unpack2(add2(add2(v0,v1), add2(v2,v3)), vx, vy);
    rr = rsqrtf((vx + vy)*(1.f/DD) + LNEPS);
}

// LN + relu + reductions for one pair. mirror=false: bq2 += b, colsum->svp2.
// mirror=true: bpa[lane] += b, colsum->svq2.
__device__ __forceinline__ void emit_pair(PairSmem* sm, int w, int lane, int ii,
                                          ull* acc, ull* bq2, bool mirror) {
    float m, rr; ln_stats(acc, m, rr);
    float mr = -m*rr;
    ull r2 = pack2(rr, rr), mr2 = pack2(mr, mr);
    ull (*bt)[33] = sm->bt[w];
    #pragma unroll
    for (int q=0; q<32; q++) {
        ull f = mr2; fma2(f, acc[q], r2);       // f = acc*r - m*r
        float b0, b1; unpack2(f, b0, b1);
        b0 = fmaxf(b0, 0.f); b1 = fmaxf(b1, 0.f);
        ull b2 = pack2(b0, b1);
        if (!mirror) bq2[q] = add2(bq2[q], b2);
        else { ull* bp = &sm->bpa[w][lane][q]; *bp = add2(*bp, b2); }
        bt[lane][q] = b2;
    }
    __syncwarp();
    ull s2 = 0ull;
    #pragma unroll
    for (int r=0; r<32; r++) s2 = add2(s2, bt[r][lane]);
    ull (*sv)[33] = mirror ? sm->svq2 : sm->svp2;
    sv[ii][lane] = add2(sv[ii][lane], s2);
    __syncwarp();
}

__global__ void __launch_bounds__(256,1) k_pair(const float* __restrict__ hW,
                                                const float* __restrict__ hb) {
    extern __shared__ char smraw[];
    PairSmem* sm = reinterpret_cast<PairSmem*>(smraw);
    int t = threadIdx.x;

    // triangular tile decode: 136 blocks, bi <= bj
    int bi = 0, rem = blockIdx.x;
    while (rem >= 16 - bi) { rem -= 16 - bi; bi++; }
    int bj = bi + rem;
    int i0 = bi*64, j0 = bj*64;
    bool diag = (bi == bj);

    float* hwf = reinterpret_cast<float*>(sm->hw2);
    ull*   svpf = &sm->svp2[0][0];
    ull*   svqf = &sm->svq2[0][0];
    #pragma unroll
    for (int r=0; r<16; r++) {
        int idx = t + r*256;
        int row = idx>>6, k = idx&63;
        sm->hiT[k][row] = d_h[(i0+row)*DD + k];
        sm->hjT[k][row] = d_h[(j0+row)*DD + k];
        hwf[idx] = hW[idx];
    }
    for (int idx=t; idx<DD*33; idx+=256) { svpf[idx] = 0ull; svqf[idx] = 0ull; }
    if (t < DD) {
        reinterpret_cast<float*>(sm->hwe2)[t] = hW[DD*DD + t];
        reinterpret_cast<float*>(sm->hb2)[t]  = hb[t];
    }
    if (t < 128) {
        int r = t>>1, wd = t&1;
        sm->bm0[r][wd] = d_bitmap[((unsigned)(i0+r)*NN + (unsigned)j0)/32 + wd];
        sm->bm1[r][wd] = d_bitmap[((unsigned)(j0+r)*NN + (unsigned)i0)/32 + wd];
    }
    __syncthreads();

    int lane = t & 31, w = t >> 5;
    ull accA[32], accB[32], bq2[32];

    for (int jt=0; jt<2; jt++) {
        int jj = lane + 32*jt;
        #pragma unroll
        for (int q=0; q<32; q++) bq2[q] = 0ull;
        if (!diag) {
            #pragma unroll
            for (int q=0; q<32; q++) sm->bpa[w][lane][q] = 0ull;
        }

        for (int it4=0; it4<4; it4++) {
            int ii0 = w*8 + it4*2, ii1 = ii0 + 1;
            #pragma unroll
            for (int q=0; q<32; q++) { accA[q] = sm->hb2[q]; accB[q] = sm->hb2[q]; }

            #pragma unroll 4
            for (int k=0; k<DD; k++) {
                float hj = sm->hjT[k][jj];
                float a0 = sm->hiT[k][ii0] * hj;
                float a1 = sm->hiT[k][ii1] * hj;
                ull a02 = pack2(a0, a0);
                ull a12 = pack2(a1, a1);
                #pragma unroll
                for (int q=0; q<16; q++) {
                    ulonglong2 wv = sm->hw2[k][q];
                    fma2(accA[2*q],   a02, wv.x);
                    fma2(accA[2*q+1], a02, wv.y);
                    fma2(accB[2*q],   a12, wv.x);
                    fma2(accB[2*q+1], a12, wv.y);
                }
            }
            int jw = jj >> 5, jb = jj & 31;
            float e0 = (sm->bm0[ii0][jw] >> jb) & 1u ? 1.f : 0.f;
            float e1 = (sm->bm0[ii1][jw] >> jb) & 1u ? 1.f : 0.f;
            ull e0p = pack2(e0, e0), e1p = pack2(e1, e1);
            #pragma unroll
            for (int q=0; q<32; q++) {
                fma2(accA[q], e0p, sm->hwe2[q]);
                fma2(accB[q], e1p, sm->hwe2[q]);
            }

            emit_pair(sm, w, lane, ii0, accA, bq2, false);
            if (!diag) {
                float em = (sm->bm1[jj][ii0>>5] >> (ii0&31)) & 1u ? 1.f : 0.f;
                ull dp = pack2(em - e0, em - e0);
                #pragma unroll
                for (int q=0; q<32; q++) fma2(accA[q], dp, sm->hwe2[q]);
                emit_pair(sm, w, lane, ii0, accA, bq2, true);
            }
            emit_pair(sm, w, lane, ii1, accB, bq2, false);
            if (!diag) {
                float em = (sm->bm1[jj][ii1>>5] >> (ii1&31)) & 1u ? 1.f : 0.f;
                ull dp = pack2(em - e1, em - e1);
                #pragma unroll
                for (int q=0; q<32; q++) fma2(accB[q], dp, sm->hwe2[q]);
                emit_pair(sm, w, lane, ii1, accB, bq2, true);
            }
        }

        // ---- flush bq2 (vq) and bpa (mirror vp) for this jt ----
        #pragma unroll
        for (int q=0; q<32; q++) sm->bt[w][lane][q] = bq2[q];
        __syncthreads();
        for (int idx=t; idx<1024; idx+=256) {
            int r = idx>>5, q = idx&31;
            ull s = 0ull;
            #pragma unroll
            for (int ww=0; ww<8; ww++) s = add2(s, sm->bt[ww][r][q]);
            float x0, x1; unpack2(s, x0, x1);
            atomicAdd(&d_vecq[(j0 + 32*jt + r)*DD + 2*q],     x0);
            atomicAdd(&d_vecq[(j0 + 32*jt + r)*DD + 2*q + 1], x1);
        }
        if (!diag) {
            for (int idx=t; idx<1024; idx+=256) {
                int r = idx>>5, q = idx&31;
                ull s = 0ull;
                #pragma unroll
                for (int ww=0; ww<8; ww++) s = add2(s, sm->bpa[ww][r][q]);
                float x0, x1; unpack2(s, x0, x1);
                atomicAdd(&d_vecp[(j0 + 32*jt + r)*DD + 2*q],     x0);
                atomicAdd(&d_vecp[(j0 + 32*jt + r)*DD + 2*q + 1], x1);
            }
        }
        __syncthreads();
    }

    // ---- flush block i-row accumulators ----
    for (int idx=t; idx<DD*32; idx+=256) {
        int ii = idx>>5, q = idx&31;
        float x0, x1;
        unpack2(sm->svp2[ii][q], x0, x1);
        atomicAdd(&d_vecp[(i0+ii)*DD + 2*q],     x0);
        atomicAdd(&d_vecp[(i0+ii)*DD + 2*q + 1], x1);
        if (!diag) {
            unpack2(sm->svq2[ii][q], x0, x1);
            atomicAdd(&d_vecq[(i0+ii)*DD + 2*q],     x0);
            atomicAdd(&d_vecq[(i0+ii)*DD + 2*q + 1], x1);
        }
    }
}

// ------------------------- phase C ------------------------------------------
__global__ void k_prec(const float* __restrict__ gW) {
    __shared__ float s_v[DD];
    int i = blockIdx.x, c = threadIdx.x;
    int which = blockIdx.y;
    const float* src = which ? d_vecq : d_vecp;
    const float* w   = gW + (which ? 129 : 65)*DD;
    float*       dst = which ? d_VQ : d_VP;
    s_v[c] = src[i*DD + c];
    __syncthreads();
    float acc = 0.f;
    #pragma unroll 8
    for (int k=0; k<DD; k++) acc = fmaf(s_v[k], w[k*DD+c], acc);
    dst[i*DD + c] = acc;
}

__global__ void k_gpairs(const int* __restrict__ pos, const float* __restrict__ gW,
                         const float* __restrict__ gb) {
    __shared__ float sgw[DD+1][DD];
    __shared__ float sgb[DD];
    int t = threadIdx.x;
    for (int idx=t; idx<(DD+1)*DD; idx+=256) sgw[idx>>6][idx&63] = gW[idx];
    if (t < DD) sgb[t] = gb[t];
    __syncthreads();

    int gt = blockIdx.x*256 + t;
    int p = gt >> 5, lane = gt & 31;
    if (p >= 2*NP) return;
    int i, j;
    if (p < NP) { i = pos[2*p];         j = pos[2*p+1];      }
    else        { i = pos[2*(p-NP)+1];  j = pos[2*(p-NP)];   }
    int c0 = lane, c1 = lane + 32;
    const float* hi = d_h + i*DD;
    const float* hj = d_h + j*DD;
    float a0 = sgb[c0] + d_VP[i*DD+c0] + d_VQ[j*DD+c0];
    float a1 = sgb[c1] + d_VP[i*DD+c1] + d_VQ[j*DD+c1];
    unsigned bidx = (unsigned)i*NN + (unsigned)j;
    float e = ((d_bitmap[bidx>>5] >> (bidx & 31u)) & 1u) ? 1.f : 0.f;
    a0 = fmaf(e, sgw[DD][c0], a0);
    a1 = fmaf(e, sgw[DD][c1], a1);
    #pragma unroll 8
    for (int k=0; k<DD; k++) {
        float a = hi[k]*hj[k];
        a0 = fmaf(a, sgw[k][c0], a0);
        a1 = fmaf(a, sgw[k][c1], a1);
    }
    float s = a0 + a1;
    s += __shfl_xor_sync(0xffffffffu, s, 16);
    s += __shfl_xor_sync(0xffffffffu, s, 8);
    s += __shfl_xor_sync(0xffffffffu, s, 4);
    s += __shfl_xor_sync(0xffffffffu, s, 2);
    s += __shfl_xor_sync(0xffffffffu, s, 1);
    float m = s*(1.f/DD);
    float e0 = a0 - m, e1 = a1 - m;
    float vv = e0*e0 + e1*e1;
    vv += __shfl_xor_sync(0xffffffffu, vv, 16);
    vv += __shfl_xor_sync(0xffffffffu, vv, 8);
    vv += __shfl_xor_sync(0xffffffffu, vv, 4);
    vv += __shfl_xor_sync(0xffffffffu, vv, 2);
    vv += __shfl_xor_sync(0xffffffffu, vv, 1);
    float r = rsqrtf(vv*(1.f/DD) + LNEPS);
    d_G[p*DD + c0] = fmaxf(e0*r, 0.f);
    d_G[p*DD + c1] = fmaxf(e1*r, 0.f);
}

__global__ void k_out(const float* __restrict__ linW, const float* __restrict__ linb,
                      float* __restrict__ out) {
    int gt = blockIdx.x*blockDim.x + threadIdx.x;
    int p = gt >> 5, lane = gt & 31;
    if (p >= NP) return;
    float s = d_G[p*DD + lane]      * d_G[(p+NP)*DD + lane]      * linW[lane]
            + d_G[p*DD + lane + 32] * d_G[(p+NP)*DD + lane + 32] * linW[lane + 32];
    s += __shfl_xor_sync(0xffffffffu, s, 16);
    s += __shfl_xor_sync(0xffffffffu, s, 8);
    s += __shfl_xor_sync(0xffffffffu, s, 4);
    s += __shfl_xor_sync(0xffffffffu, s, 2);
    s += __shfl_xor_sync(0xffffffffu, s, 1);
    if (lane == 0) out[p] = s + linb[0];
}

// ------------------------- launch -------------------------------------------
extern "C" void kernel_launch(void* const* d_in, const int* in_sizes, int n_in,
                              void* d_out, int out_size) {
    const int*   x   = (const int*)d_in[0];
    const int*   ei  = (const int*)d_in[1];
    const int*   pos = (const int*)d_in[2];
    const float* emb = (const float*)d_in[3];
    const float* sWl = (const float*)d_in[4];
    const float* sbl = (const float*)d_in[5];
    const float* sWr = (const float*)d_in[6];
    const float* hW  = (const float*)d_in[7];
    const float* hb  = (const float*)d_in[8];
    const float* gW  = (const float*)d_in[9];
    const float* gb  = (const float*)d_in[10];
    const float* lW  = (const float*)d_in[11];
    const float* lb  = (const float*)d_in[12];
    float* out = (float*)d_out;

    cudaFuncSetAttribute(k_pair, cudaFuncAttributeMaxDynamicSharedMemorySize,
                         (int)sizeof(PairSmem));

    k_init<<<256, 256>>>(x, emb);
    k_scat0<<<NE*DD/256, 256>>>(ei);
    k_sage<<<NN, DD>>>(sWl, sbl, sWr, 0);
    k_scatter<<<NE*DD/256, 256>>>(ei);
    k_sage<<<NN, DD>>>(sWl, sbl, sWr, 1);
    k_pair<<<136, 256, sizeof(PairSmem)>>>(hW, hb);
    k_prec<<<dim3(NN,2), DD>>>(gW);
    k_gpairs<<<(2*NP*32)/256, 256>>>(pos, gW, gb);
    k_out<<<(NP*32)/256, 256>>>(lW, lb, out);
}

// round 7
// speedup vs baseline: 3.6661x; 1.3918x over previous
#include <cuda_runtime.h>
#include <cstdint>

#define NN 1024
#define DD 64
#define NE 16384
#define NP 8192
#define LNEPS 1e-5f

// ------------------------- helpers ------------------------------------------
__device__ __forceinline__ uint32_t cvt_tf32(float f) {
    uint32_t u; asm("cvt.rna.tf32.f32 %0, %1;" : "=r"(u) : "f"(f)); return u;
}
__device__ __forceinline__ void mma_tf32(float* d, uint32_t a0, uint32_t a1,
                                         uint32_t a2, uint32_t a3,
                                         uint32_t b0, uint32_t b1) {
    asm volatile(
        "mma.sync.aligned.m16n8k8.row.col.f32.tf32.tf32.f32 "
        "{%0,%1,%2,%3}, {%4,%5,%6,%7}, {%8,%9}, {%0,%1,%2,%3};"
        : "+f"(d[0]), "+f"(d[1]), "+f"(d[2]), "+f"(d[3])
        : "r"(a0), "r"(a1), "r"(a2), "r"(a3), "r"(b0), "r"(b1));
}

// ------------------------- scratch (device globals) -------------------------
__device__ float    d_h[NN*DD];
__device__ float    d_hn[NN*DD];
__device__ float    d_aggr[NN*DD];
__device__ float    d_deg[NN];
__device__ unsigned d_bitmap[NN*NN/32];
__device__ float    d_vecp[NN*DD];
__device__ float    d_vecq[NN*DD];
__device__ float    d_VP[NN*DD];
__device__ float    d_VQ[NN*DD];

// ------------------------- phase A ------------------------------------------
__global__ void k_init(const int* __restrict__ x, const float* __restrict__ emb) {
    int t  = blockIdx.x*blockDim.x + threadIdx.x;
    int st = gridDim.x*blockDim.x;
    for (int i=t; i<NN*NN/32; i+=st) d_bitmap[i] = 0u;
    for (int i=t; i<NN;       i+=st) d_deg[i]    = 0.f;
    for (int i=t; i<NN*DD;    i+=st) {
        d_vecp[i]=0.f; d_vecq[i]=0.f; d_aggr[i]=0.f;
        d_h[i] = emb[x[i>>6]*DD + (i&63)];
    }
}

__global__ void k_scat0(const int* __restrict__ ei) {
    int t = blockIdx.x*blockDim.x + threadIdx.x;
    if (t < NE*DD) {
        int e = t>>6, c = t&63;
        int s = ei[e], d = ei[NE+e];
        atomicAdd(&d_aggr[d*DD + c], d_h[s*DD + c]);
        if (c == 0) {
            atomicAdd(&d_deg[d], 1.f);
            unsigned idx = (unsigned)s*NN + (unsigned)d;
            atomicOr(&d_bitmap[idx>>5], 1u << (idx & 31u));
        }
    }
}

__global__ void k_scatter(const int* __restrict__ ei) {
    int t = blockIdx.x*blockDim.x + threadIdx.x;
    if (t < NE*DD) {
        int e = t>>6, c = t&63;
        atomicAdd(&d_aggr[ei[NE+e]*DD + c], d_hn[ei[e]*DD + c]);
    }
}

__global__ void k_sage(const float* __restrict__ Wl, const float* __restrict__ bl,
                       const float* __restrict__ Wr, int layer) {
    __shared__ float s_in[DD], s_ag[DD], s_red[DD];
    int i = blockIdx.x, c = threadIdx.x;
    const float* hs = layer ? d_hn : d_h;
    float*       hd = layer ? d_h  : d_hn;
    float dg = fmaxf(d_deg[i], 1.f);
    s_in[c] = hs[i*DD+c];
    s_ag[c] = d_aggr[i*DD+c] / dg;
    d_aggr[i*DD+c] = 0.f;
    __syncthreads();
    const float* wl = Wl + layer*DD*DD;
    const float* wr = Wr + layer*DD*DD;
    float acc = bl[layer*DD + c];
    #pragma unroll 8
    for (int k=0; k<DD; k++)
        acc = fmaf(s_ag[k], wl[k*DD+c], fmaf(s_in[k], wr[k*DD+c], acc));
    s_red[c] = acc;
    __syncthreads();
    float m = 0.f;
    #pragma unroll 8
    for (int k=0; k<DD; k++) m += s_red[k];
    m *= (1.f/DD);
    float v = 0.f;
    #pragma unroll 8
    for (int k=0; k<DD; k++) { float dd0 = s_red[k]-m; v = fmaf(dd0, dd0, v); }
    v *= (1.f/DD);
    hd[i*DD+c] = (acc - m) * rsqrtf(v + LNEPS);
}

// ------------------------- phase B: mma.sync tf32 pair kernel ---------------
struct PairSmem {
    float    hi_s[64][68];     // h rows i-block   [row][k]
    float    hj_s[64][68];     // h rows j-block
    float    wtf[64][72];      // W (tf32-rounded) [k][n], stride 72: conflict-free
    float    st[8][16][68];    // per-warp b staging (normal)
    float    st2[8][16][68];   // per-warp b staging (mirror)
    float    vqa[64][68];      // vq accum by jj (normal)
    float    vqa2[64][68];     // vecp accum by jj (mirror)
    float    svp[64][68];      // vp accum by ii (normal)
    float    svq2[64][68];     // vecq accum by ii (mirror)
    float    hwe[64], hbias[64];
    unsigned bm0[64][2], bm1[64][2];
};

__device__ __forceinline__ void ln16(const float* pre, float& m, float& r) {
    float s = 0.f;
    #pragma unroll
    for (int i=0;i<16;i++) s += pre[i];
    s += __shfl_xor_sync(0xffffffffu, s, 1);
    s += __shfl_xor_sync(0xffffffffu, s, 2);
    m = s * (1.f/DD);
    float v = 0.f;
    #pragma unroll
    for (int i=0;i<16;i++) { float d = pre[i]-m; v = fmaf(d,d,v); }
    v += __shfl_xor_sync(0xffffffffu, v, 1);
    v += __shfl_xor_sync(0xffffffffu, v, 2);
    r = rsqrtf(v*(1.f/DD) + LNEPS);
}

__global__ void __launch_bounds__(256,1) k_pair(const float* __restrict__ hW,
                                                const float* __restrict__ hb) {
    extern __shared__ char smraw[];
    PairSmem* sm = reinterpret_cast<PairSmem*>(smraw);
    int t = threadIdx.x;
    int lane = t & 31, w = t >> 5;
    int g = lane >> 2, tg = lane & 3;

    // triangular tile decode
    int bi = 0, rem = blockIdx.x;
    while (rem >= 16 - bi) { rem -= 16 - bi; bi++; }
    int bj = bi + rem;
    int i0 = bi*64, j0 = bj*64;
    bool diag = (bi == bj);

    // ---- stage ----
    for (int idx=t; idx<DD*DD; idx+=256) {
        int r = idx>>6, k = idx&63;
        sm->hi_s[r][k] = d_h[(i0+r)*DD + k];
        sm->hj_s[r][k] = d_h[(j0+r)*DD + k];
        sm->wtf[r][k]  = __uint_as_float(cvt_tf32(hW[r*DD + k]));  // [k=r][n=k]
    }
    for (int idx=t; idx<DD*68; idx+=256) {
        sm->vqa [idx/68][idx%68] = 0.f;
        sm->vqa2[idx/68][idx%68] = 0.f;
        sm->svp [idx/68][idx%68] = 0.f;
        sm->svq2[idx/68][idx%68] = 0.f;
    }
    if (t < DD) { sm->hwe[t] = hW[DD*DD + t]; sm->hbias[t] = hb[t]; }
    if (t < 128) {
        int r = t>>1, wd = t&1;
        sm->bm0[r][wd] = d_bitmap[((unsigned)(i0+r)*NN + (unsigned)j0)/32 + wd];
        sm->bm1[r][wd] = d_bitmap[((unsigned)(j0+r)*NN + (unsigned)i0)/32 + wd];
    }
    __syncthreads();

    // per-thread channel constants: ch(i) = (i>>1)*8 + 2*tg + (i&1)
    float hb_r[16], we_r[16];
    #pragma unroll
    for (int i=0;i<16;i++) {
        int ch = (i>>1)*8 + 2*tg + (i&1);
        hb_r[i] = sm->hbias[ch];
        we_r[i] = sm->hwe[ch];
    }

    for (int s=0; s<32; s++) {
        int jjq = s & 7, ii0 = (s>>3) << 4;
        int jj = w*8 + jjq;

        float acc[8][4];
        #pragma unroll
        for (int nt=0; nt<8; nt++) { acc[nt][0]=acc[nt][1]=acc[nt][2]=acc[nt][3]=0.f; }

        #pragma unroll
        for (int kt=0; kt<8; kt++) {
            int k0 = kt*8 + tg, k1 = k0 + 4;
            float hj0 = sm->hj_s[jj][k0], hj1 = sm->hj_s[jj][k1];
            float hi00 = sm->hi_s[ii0+g][k0],   hi01 = sm->hi_s[ii0+g][k1];
            float hi80 = sm->hi_s[ii0+g+8][k0], hi81 = sm->hi_s[ii0+g+8][k1];
            uint32_t a0 = cvt_tf32(hi00*hj0);
            uint32_t a1 = cvt_tf32(hi80*hj0);
            uint32_t a2 = cvt_tf32(hi01*hj1);
            uint32_t a3 = cvt_tf32(hi81*hj1);
            #pragma unroll
            for (int nt=0; nt<8; nt++) {
                uint32_t b0 = __float_as_uint(sm->wtf[k0][nt*8+g]);
                uint32_t b1 = __float_as_uint(sm->wtf[k1][nt*8+g]);
                mma_tf32(acc[nt], a0, a1, a2, a3, b0, b1);
            }
        }

        // ---- edge + bias ----
        float e_g  = ((sm->bm0[ii0+g  ][jj>>5] >> (jj&31)) & 1u) ? 1.f : 0.f;
        float e_g8 = ((sm->bm0[ii0+g+8][jj>>5] >> (jj&31)) & 1u) ? 1.f : 0.f;
        float pre0[16], pre1[16];
        #pragma unroll
        for (int nt=0; nt<8; nt++) {
            #pragma unroll
            for (int hf=0; hf<2; hf++) {
                int i = 2*nt + hf;
                pre0[i] = acc[nt][hf]   + hb_r[i] + e_g *we_r[i];
                pre1[i] = acc[nt][2+hf] + hb_r[i] + e_g8*we_r[i];
            }
        }

        // ---- LN + relu + emissions (normal: pair (i0+ii, j0+jj)) ----
        float m0, r0, m1, r1, vs[16];
        ln16(pre0, m0, r0);
        ln16(pre1, m1, r1);
        #pragma unroll
        for (int nt=0; nt<8; nt++) {
            int i0i = 2*nt, i1i = i0i+1;
            float b00 = fmaxf((pre0[i0i]-m0)*r0, 0.f);
            float b01 = fmaxf((pre0[i1i]-m0)*r0, 0.f);
            float b10 = fmaxf((pre1[i0i]-m1)*r1, 0.f);
            float b11 = fmaxf((pre1[i1i]-m1)*r1, 0.f);
            vs[i0i] = b00 + b10; vs[i1i] = b01 + b11;
            int ch0 = nt*8 + 2*tg;
            *reinterpret_cast<float2*>(&sm->st[w][g  ][ch0]) = make_float2(b00, b01);
            *reinterpret_cast<float2*>(&sm->st[w][g+8][ch0]) = make_float2(b10, b11);
        }
        #pragma unroll
        for (int msk=4; msk<=16; msk<<=1) {
            #pragma unroll
            for (int i=0;i<16;i++) vs[i] += __shfl_xor_sync(0xffffffffu, vs[i], msk);
        }
        if (g == 0) {
            #pragma unroll
            for (int nt=0; nt<8; nt++) {
                int ch0 = nt*8 + 2*tg;
                float2* p = reinterpret_cast<float2*>(&sm->vqa[jj][ch0]);
                float2 v = *p; v.x += vs[2*nt]; v.y += vs[2*nt+1]; *p = v;
            }
        }

        // ---- mirror: pair (j0+jj, i0+ii) ----
        if (!diag) {
            float ep_g  = ((sm->bm1[jj][(ii0+g  )>>5] >> ((ii0+g  )&31)) & 1u) ? 1.f : 0.f;
            float ep_g8 = ((sm->bm1[jj][(ii0+g+8)>>5] >> ((ii0+g+8)&31)) & 1u) ? 1.f : 0.f;
            float d0 = ep_g - e_g, d1 = ep_g8 - e_g8;
            #pragma unroll
            for (int i=0;i<16;i++) { pre0[i] = fmaf(d0, we_r[i], pre0[i]);
                                     pre1[i] = fmaf(d1, we_r[i], pre1[i]); }
            ln16(pre0, m0, r0);
            ln16(pre1, m1, r1);
            #pragma unroll
            for (int nt=0; nt<8; nt++) {
                int i0i = 2*nt, i1i = i0i+1;
                float b00 = fmaxf((pre0[i0i]-m0)*r0, 0.f);
                float b01 = fmaxf((pre0[i1i]-m0)*r0, 0.f);
                float b10 = fmaxf((pre1[i0i]-m1)*r1, 0.f);
                float b11 = fmaxf((pre1[i1i]-m1)*r1, 0.f);
                vs[i0i] = b00 + b10; vs[i1i] = b01 + b11;
                int ch0 = nt*8 + 2*tg;
                *reinterpret_cast<float2*>(&sm->st2[w][g  ][ch0]) = make_float2(b00, b01);
                *reinterpret_cast<float2*>(&sm->st2[w][g+8][ch0]) = make_float2(b10, b11);
            }
            #pragma unroll
            for (int msk=4; msk<=16; msk<<=1) {
                #pragma unroll
                for (int i=0;i<16;i++) vs[i] += __shfl_xor_sync(0xffffffffu, vs[i], msk);
            }
            if (g == 0) {
                #pragma unroll
                for (int nt=0; nt<8; nt++) {
                    int ch0 = nt*8 + 2*tg;
                    float2* p = reinterpret_cast<float2*>(&sm->vqa2[jj][ch0]);
                    float2 v = *p; v.x += vs[2*nt]; v.y += vs[2*nt+1]; *p = v;
                }
            }
        }
        __syncthreads();

        // ---- block reduce staged tiles into per-ii accumulators ----
        {
            int r = t >> 4, cq = (t & 15) * 4;
            float4 s4 = make_float4(0.f,0.f,0.f,0.f);
            #pragma unroll
            for (int ww=0; ww<8; ww++) {
                float4 v = *reinterpret_cast<float4*>(&sm->st[ww][r][cq]);
                s4.x += v.x; s4.y += v.y; s4.z += v.z; s4.w += v.w;
            }
            float4* d4 = reinterpret_cast<float4*>(&sm->svp[ii0+r][cq]);
            float4 o = *d4;
            o.x += s4.x; o.y += s4.y; o.z += s4.z; o.w += s4.w;
            *d4 = o;
            if (!diag) {
                float4 s5 = make_float4(0.f,0.f,0.f,0.f);
                #pragma unroll
                for (int ww=0; ww<8; ww++) {
                    float4 v = *reinterpret_cast<float4*>(&sm->st2[ww][r][cq]);
                    s5.x += v.x; s5.y += v.y; s5.z += v.z; s5.w += v.w;
                }
                float4* d5 = reinterpret_cast<float4*>(&sm->svq2[ii0+r][cq]);
                float4 o2 = *d5;
                o2.x += s5.x; o2.y += s5.y; o2.z += s5.z; o2.w += s5.w;
                *d5 = o2;
            }
        }
        __syncthreads();
    }

    // ---- flush ----
    for (int idx=t; idx<DD*DD; idx+=256) {
        int rr = idx>>6, ch = idx&63;
        atomicAdd(&d_vecp[(i0+rr)*DD + ch], sm->svp[rr][ch]);
        atomicAdd(&d_vecq[(j0+rr)*DD + ch], sm->vqa[rr][ch]);
        if (!diag) {
            atomicAdd(&d_vecq[(i0+rr)*DD + ch], sm->svq2[rr][ch]);
            atomicAdd(&d_vecp[(j0+rr)*DD + ch], sm->vqa2[rr][ch]);
        }
    }
}

// ------------------------- phase C ------------------------------------------
__global__ void k_prec(const float* __restrict__ gW) {
    __shared__ float s_v[DD];
    int i = blockIdx.x, c = threadIdx.x;
    int which = blockIdx.y;
    const float* src = which ? d_vecq : d_vecp;
    const float* w   = gW + (which ? 129 : 65)*DD;
    float*       dst = which ? d_VQ : d_VP;
    s_v[c] = src[i*DD + c];
    __syncthreads();
    float acc = 0.f;
    #pragma unroll 8
    for (int k=0; k<DD; k++) acc = fmaf(s_v[k], w[k*DD+c], acc);
    dst[i*DD + c] = acc;
}

// fused: both orientations + elementwise product + linear output
__global__ void k_gpairs(const int* __restrict__ pos, const float* __restrict__ gW,
                         const float* __restrict__ gb, const float* __restrict__ lW,
                         const float* __restrict__ lb, float* __restrict__ out) {
    __shared__ float sgw[DD+1][DD];
    __shared__ float sgb[DD], slw[DD];
    int t = threadIdx.x;
    for (int idx=t; idx<(DD+1)*DD; idx+=256) sgw[idx>>6][idx&63] = gW[idx];
    if (t < DD) { sgb[t] = gb[t]; slw[t] = lW[t]; }
    __syncthreads();

    int gt = blockIdx.x*256 + t;
    int p = gt >> 5, lane = gt & 31;
    if (p >= NP) return;
    int i = pos[2*p], j = pos[2*p+1];
    int c0 = lane, c1 = lane + 32;
    const float* hi = d_h + i*DD;
    const float* hj = d_h + j*DD;

    float g0 = 0.f, g1 = 0.f;
    #pragma unroll 8
    for (int k=0; k<DD; k++) {
        float a = hi[k]*hj[k];
        g0 = fmaf(a, sgw[k][c0], g0);
        g1 = fmaf(a, sgw[k][c1], g1);
    }
    unsigned bij = (unsigned)i*NN + (unsigned)j;
    unsigned bji = (unsigned)j*NN + (unsigned)i;
    float eij = ((d_bitmap[bij>>5] >> (bij & 31u)) & 1u) ? 1.f : 0.f;
    float eji = ((d_bitmap[bji>>5] >> (bji & 31u)) & 1u) ? 1.f : 0.f;

    float aA0 = g0 + sgb[c0] + d_VP[i*DD+c0] + d_VQ[j*DD+c0] + eij*sgw[DD][c0];
    float aA1 = g1 + sgb[c1] + d_VP[i*DD+c1] + d_VQ[j*DD+c1] + eij*sgw[DD][c1];
    float aB0 = g0 + sgb[c0] + d_VP[j*DD+c0] + d_VQ[i*DD+c0] + eji*sgw[DD][c0];
    float aB1 = g1 + sgb[c1] + d_VP[j*DD+c1] + d_VQ[i*DD+c1] + eji*sgw[DD][c1];

    float s = aA0 + aA1;
    #pragma unroll
    for (int o=16; o>=1; o>>=1) s += __shfl_xor_sync(0xffffffffu, s, o);
    float mA = s*(1.f/DD);
    float dA0 = aA0-mA, dA1 = aA1-mA;
    float v = dA0*dA0 + dA1*dA1;
    #pragma unroll
    for (int o=16; o>=1; o>>=1) v += __shfl_xor_sync(0xffffffffu, v, o);
    float rA = rsqrtf(v*(1.f/DD) + LNEPS);
    float GA0 = fmaxf(dA0*rA, 0.f), GA1 = fmaxf(dA1*rA, 0.f);

    s = aB0 + aB1;
    #pragma unroll
    for (int o=16; o>=1; o>>=1) s += __shfl_xor_sync(0xffffffffu, s, o);
    float mB = s*(1.f/DD);
    float dB0 = aB0-mB, dB1 = aB1-mB;
    v = dB0*dB0 + dB1*dB1;
    #pragma unroll
    for (int o=16; o>=1; o>>=1) v += __shfl_xor_sync(0xffffffffu, v, o);
    float rB = rsqrtf(v*(1.f/DD) + LNEPS);
    float GB0 = fmaxf(dB0*rB, 0.f), GB1 = fmaxf(dB1*rB, 0.f);

    float o0 = GA0*GB0*slw[c0] + GA1*GB1*slw[c1];
    #pragma unroll
    for (int o=16; o>=1; o>>=1) o0 += __shfl_xor_sync(0xffffffffu, o0, o);
    if (lane == 0) out[p] = o0 + lb[0];
}

// ------------------------- launch -------------------------------------------
extern "C" void kernel_launch(void* const* d_in, const int* in_sizes, int n_in,
                              void* d_out, int out_size) {
    const int*   x   = (const int*)d_in[0];
    const int*   ei  = (const int*)d_in[1];
    const int*   pos = (const int*)d_in[2];
    const float* emb = (const float*)d_in[3];
    const float* sWl = (const float*)d_in[4];
    const float* sbl = (const float*)d_in[5];
    const float* sWr = (const float*)d_in[6];
    const float* hW  = (const float*)d_in[7];
    const float* hb  = (const float*)d_in[8];
    const float* gW  = (const float*)d_in[9];
    const float* gb  = (const float*)d_in[10];
    const float* lW  = (const float*)d_in[11];
    const float* lb  = (const float*)d_in[12];
    float* out = (float*)d_out;

    cudaFuncSetAttribute(k_pair, cudaFuncAttributeMaxDynamicSharedMemorySize,
                         (int)sizeof(PairSmem));

    k_init<<<256, 256>>>(x, emb);
    k_scat0<<<NE*DD/256, 256>>>(ei);
    k_sage<<<NN, DD>>>(sWl, sbl, sWr, 0);
    k_scatter<<<NE*DD/256, 256>>>(ei);
    k_sage<<<NN, DD>>>(sWl, sbl, sWr, 1);
    k_pair<<<136, 256, sizeof(PairSmem)>>>(hW, hb);
    k_prec<<<dim3(NN,2), DD>>>(gW);
    k_gpairs<<<(NP*32)/256, 256>>>(pos, gW, gb, lW, lb, out);
}

// round 8
// speedup vs baseline: 3.8269x; 1.0439x over previous
#include <cuda_runtime.h>
#include <cstdint>

#define NN 1024
#define DD 64
#define NE 16384
#define NP 8192
#define LNEPS 1e-5f

// ------------------------- helpers ------------------------------------------
__device__ __forceinline__ uint32_t cvt_tf32(float f) {
    uint32_t u; asm("cvt.rna.tf32.f32 %0, %1;" : "=r"(u) : "f"(f)); return u;
}
__device__ __forceinline__ void mma_tf32(float* d, uint32_t a0, uint32_t a1,
                                         uint32_t a2, uint32_t a3,
                                         uint32_t b0, uint32_t b1) {
    asm volatile(
        "mma.sync.aligned.m16n8k8.row.col.f32.tf32.tf32.f32 "
        "{%0,%1,%2,%3}, {%4,%5,%6,%7}, {%8,%9}, {%0,%1,%2,%3};"
        : "+f"(d[0]), "+f"(d[1]), "+f"(d[2]), "+f"(d[3])
        : "r"(a0), "r"(a1), "r"(a2), "r"(a3), "r"(b0), "r"(b1));
}

// ------------------------- scratch (device globals) -------------------------
__device__ float    d_h[NN*DD];
__device__ float    d_hn[NN*DD];
__device__ float    d_aggr[NN*DD];
__device__ float    d_deg[NN];
__device__ unsigned d_bitmap[NN*NN/32];
__device__ float    d_vecp[NN*DD];
__device__ float    d_vecq[NN*DD];
__device__ float    d_VP[NN*DD];
__device__ float    d_VQ[NN*DD];

// ------------------------- phase A ------------------------------------------
__global__ void k_init(const int* __restrict__ x, const float* __restrict__ emb) {
    int t  = blockIdx.x*blockDim.x + threadIdx.x;
    int st = gridDim.x*blockDim.x;
    for (int i=t; i<NN*NN/32; i+=st) d_bitmap[i] = 0u;
    for (int i=t; i<NN;       i+=st) d_deg[i]    = 0.f;
    for (int i=t; i<NN*DD;    i+=st) {
        d_vecp[i]=0.f; d_vecq[i]=0.f; d_aggr[i]=0.f;
        d_h[i] = emb[x[i>>6]*DD + (i&63)];
    }
}

__global__ void k_scat0(const int* __restrict__ ei) {
    int t = blockIdx.x*blockDim.x + threadIdx.x;
    if (t < NE*DD) {
        int e = t>>6, c = t&63;
        int s = ei[e], d = ei[NE+e];
        atomicAdd(&d_aggr[d*DD + c], d_h[s*DD + c]);
        if (c == 0) {
            atomicAdd(&d_deg[d], 1.f);
            unsigned idx = (unsigned)s*NN + (unsigned)d;
            atomicOr(&d_bitmap[idx>>5], 1u << (idx & 31u));
        }
    }
}

__global__ void k_scatter(const int* __restrict__ ei) {
    int t = blockIdx.x*blockDim.x + threadIdx.x;
    if (t < NE*DD) {
        int e = t>>6, c = t&63;
        atomicAdd(&d_aggr[ei[NE+e]*DD + c], d_hn[ei[e]*DD + c]);
    }
}

__global__ void k_sage(const float* __restrict__ Wl, const float* __restrict__ bl,
                       const float* __restrict__ Wr, int layer) {
    __shared__ float s_in[DD], s_ag[DD], s_red[DD];
    int i = blockIdx.x, c = threadIdx.x;
    const float* hs = layer ? d_hn : d_h;
    float*       hd = layer ? d_h  : d_hn;
    float dg = fmaxf(d_deg[i], 1.f);
    s_in[c] = hs[i*DD+c];
    s_ag[c] = d_aggr[i*DD+c] / dg;
    d_aggr[i*DD+c] = 0.f;
    __syncthreads();
    const float* wl = Wl + layer*DD*DD;
    const float* wr = Wr + layer*DD*DD;
    float acc = bl[layer*DD + c];
    #pragma unroll 8
    for (int k=0; k<DD; k++)
        acc = fmaf(s_ag[k], wl[k*DD+c], fmaf(s_in[k], wr[k*DD+c], acc));
    s_red[c] = acc;
    __syncthreads();
    float m = 0.f;
    #pragma unroll 8
    for (int k=0; k<DD; k++) m += s_red[k];
    m *= (1.f/DD);
    float v = 0.f;
    #pragma unroll 8
    for (int k=0; k<DD; k++) { float dd0 = s_red[k]-m; v = fmaf(dd0, dd0, v); }
    v *= (1.f/DD);
    hd[i*DD+c] = (acc - m) * rsqrtf(v + LNEPS);
}

// ------------------------- phase B: mma.sync tf32 pair kernel ---------------
struct PairSmem {
    float    hi_s[64][68];
    float    hj_s[64][68];
    float    wtf[64][72];      // W tf32-rounded [k][n]
    float    st[8][16][68];    // warp-private accum: normal B rows (ii-local)
    float    st2[8][16][68];   // warp-private accum: mirror B rows
    float    vqa[64][68];      // vq by jj (normal)
    float    vqa2[64][68];     // vecp by jj (mirror)
    float    svp[64][68];      // vp by ii (normal)
    float    svq2[64][68];     // vecq by ii (mirror)
    float    hwe[64], hbias[64];
    unsigned bm0[64][2], bm1[64][2];
};

__device__ __forceinline__ void ln16(const float* pre, float& m, float& r) {
    float s = 0.f;
    #pragma unroll
    for (int i=0;i<16;i++) s += pre[i];
    s += __shfl_xor_sync(0xffffffffu, s, 1);
    s += __shfl_xor_sync(0xffffffffu, s, 2);
    m = s * (1.f/DD);
    float v = 0.f;
    #pragma unroll
    for (int i=0;i<16;i++) { float d = pre[i]-m; v = fmaf(d,d,v); }
    v += __shfl_xor_sync(0xffffffffu, v, 1);
    v += __shfl_xor_sync(0xffffffffu, v, 2);
    r = rsqrtf(v*(1.f/DD) + LNEPS);
}

// one emission: rows (g, g+8 local), 16 channels/thread. Accumulates into
// warp-private stacc (row sums by ii) and vqrow (col sums by jj, via butterfly).
__device__ __forceinline__ void emit(float (*stacc)[68], float* vqrow,
                                     const float* pre0, const float* pre1,
                                     int g, int tg) {
    float m0, r0, m1, r1;
    ln16(pre0, m0, r0);
    ln16(pre1, m1, r1);
    float vs[16];
    #pragma unroll
    for (int nt=0; nt<8; nt++) {
        int i0i = 2*nt, i1i = i0i+1;
        float b00 = fmaxf((pre0[i0i]-m0)*r0, 0.f);
        float b01 = fmaxf((pre0[i1i]-m0)*r0, 0.f);
        float b10 = fmaxf((pre1[i0i]-m1)*r1, 0.f);
        float b11 = fmaxf((pre1[i1i]-m1)*r1, 0.f);
        vs[i0i] = b00 + b10; vs[i1i] = b01 + b11;
        int ch0 = nt*8 + 2*tg;
        float2* pA = reinterpret_cast<float2*>(&stacc[g][ch0]);
        float2 a = *pA; a.x += b00; a.y += b01; *pA = a;
        float2* pB = reinterpret_cast<float2*>(&stacc[g+8][ch0]);
        float2 b = *pB; b.x += b10; b.y += b11; *pB = b;
    }
    #pragma unroll
    for (int msk=4; msk<=16; msk<<=1) {
        #pragma unroll
        for (int i=0;i<16;i++) vs[i] += __shfl_xor_sync(0xffffffffu, vs[i], msk);
    }
    if (g == 0) {
        #pragma unroll
        for (int nt=0; nt<8; nt++) {
            int ch0 = nt*8 + 2*tg;
            float2* p = reinterpret_cast<float2*>(&vqrow[ch0]);
            float2 v = *p; v.x += vs[2*nt]; v.y += vs[2*nt+1]; *p = v;
        }
    }
}

__global__ void __launch_bounds__(256,1) k_pair(const float* __restrict__ hW,
                                                const float* __restrict__ hb) {
    extern __shared__ char smraw[];
    PairSmem* sm = reinterpret_cast<PairSmem*>(smraw);
    int t = threadIdx.x;
    int lane = t & 31, w = t >> 5;
    int g = lane >> 2, tg = lane & 3;

    int bi = 0, rem = blockIdx.x;
    while (rem >= 16 - bi) { rem -= 16 - bi; bi++; }
    int bj = bi + rem;
    int i0 = bi*64, j0 = bj*64;
    bool diag = (bi == bj);

    for (int idx=t; idx<DD*DD; idx+=256) {
        int r = idx>>6, k = idx&63;
        sm->hi_s[r][k] = d_h[(i0+r)*DD + k];
        sm->hj_s[r][k] = d_h[(j0+r)*DD + k];
        sm->wtf[r][k]  = __uint_as_float(cvt_tf32(hW[r*DD + k]));
    }
    for (int idx=t; idx<DD*68; idx+=256) {
        sm->vqa [idx/68][idx%68] = 0.f;
        sm->vqa2[idx/68][idx%68] = 0.f;
        sm->svp [idx/68][idx%68] = 0.f;
        sm->svq2[idx/68][idx%68] = 0.f;
    }
    if (t < DD) { sm->hwe[t] = hW[DD*DD + t]; sm->hbias[t] = hb[t]; }
    if (t < 128) {
        int r = t>>1, wd = t&1;
        sm->bm0[r][wd] = d_bitmap[((unsigned)(i0+r)*NN + (unsigned)j0)/32 + wd];
        sm->bm1[r][wd] = d_bitmap[((unsigned)(j0+r)*NN + (unsigned)i0)/32 + wd];
    }
    __syncthreads();

    float hb_r[16], we_r[16];
    #pragma unroll
    for (int i=0;i<16;i++) {
        int ch = (i>>1)*8 + 2*tg + (i&1);
        hb_r[i] = sm->hbias[ch];
        we_r[i] = sm->hwe[ch];
    }

    for (int i0b=0; i0b<4; i0b++) {
        int ii0 = i0b*16;
        // zero warp-private accumulators (thread-cooperative within warp)
        {
            float4 z = make_float4(0.f,0.f,0.f,0.f);
            float* stf  = &sm->st [w][0][0];
            float* st2f = &sm->st2[w][0][0];
            for (int idx=lane; idx<16*17; idx+=32) {
                *reinterpret_cast<float4*>(stf  + idx*4) = z;
                *reinterpret_cast<float4*>(st2f + idx*4) = z;
            }
        }
        __syncwarp();

        for (int q=0; q<4; q++) {
            int jjA = w*8 + 2*q, jjB = jjA + 1;

            float accA[8][4], accB[8][4];
            #pragma unroll
            for (int nt=0; nt<8; nt++) {
                accA[nt][0]=accA[nt][1]=accA[nt][2]=accA[nt][3]=0.f;
                accB[nt][0]=accB[nt][1]=accB[nt][2]=accB[nt][3]=0.f;
            }

            #pragma unroll
            for (int kt=0; kt<8; kt++) {
                int k0 = kt*8 + tg, k1 = k0 + 4;
                float hjA0 = sm->hj_s[jjA][k0], hjA1 = sm->hj_s[jjA][k1];
                float hjB0 = sm->hj_s[jjB][k0], hjB1 = sm->hj_s[jjB][k1];
                float hi00 = sm->hi_s[ii0+g][k0],   hi01 = sm->hi_s[ii0+g][k1];
                float hi80 = sm->hi_s[ii0+g+8][k0], hi81 = sm->hi_s[ii0+g+8][k1];
                uint32_t aA0 = cvt_tf32(hi00*hjA0);
                uint32_t aA1 = cvt_tf32(hi80*hjA0);
                uint32_t aA2 = cvt_tf32(hi01*hjA1);
                uint32_t aA3 = cvt_tf32(hi81*hjA1);
                uint32_t aB0 = cvt_tf32(hi00*hjB0);
                uint32_t aB1 = cvt_tf32(hi80*hjB0);
                uint32_t aB2 = cvt_tf32(hi01*hjB1);
                uint32_t aB3 = cvt_tf32(hi81*hjB1);
                #pragma unroll
                for (int nt=0; nt<8; nt++) {
                    uint32_t b0 = __float_as_uint(sm->wtf[k0][nt*8+g]);
                    uint32_t b1 = __float_as_uint(sm->wtf[k1][nt*8+g]);
                    mma_tf32(accA[nt], aA0, aA1, aA2, aA3, b0, b1);
                    mma_tf32(accB[nt], aB0, aB1, aB2, aB3, b0, b1);
                }
            }

            // ---- emissions for jjA then jjB ----
            #pragma unroll
            for (int half=0; half<2; half++) {
                int jj = half ? jjB : jjA;
                float (*acc)[4] = half ? accB : accA;
                float e_g  = ((sm->bm0[ii0+g  ][jj>>5] >> (jj&31)) & 1u) ? 1.f : 0.f;
                float e_g8 = ((sm->bm0[ii0+g+8][jj>>5] >> (jj&31)) & 1u) ? 1.f : 0.f;
                float pre0[16], pre1[16];
                #pragma unroll
                for (int nt=0; nt<8; nt++) {
                    #pragma unroll
                    for (int hf=0; hf<2; hf++) {
                        int i = 2*nt + hf;
                        pre0[i] = acc[nt][hf]   + hb_r[i] + e_g *we_r[i];
                        pre1[i] = acc[nt][2+hf] + hb_r[i] + e_g8*we_r[i];
                    }
                }
                emit(sm->st[w], sm->vqa[jj], pre0, pre1, g, tg);

                if (!diag) {
                    float ep_g  = ((sm->bm1[jj][(ii0+g  )>>5] >> ((ii0+g  )&31)) & 1u) ? 1.f : 0.f;
                    float ep_g8 = ((sm->bm1[jj][(ii0+g+8)>>5] >> ((ii0+g+8)&31)) & 1u) ? 1.f : 0.f;
                    float d0 = ep_g - e_g, d1 = ep_g8 - e_g8;
                    #pragma unroll
                    for (int i=0;i<16;i++) {
                        pre0[i] = fmaf(d0, we_r[i], pre0[i]);
                        pre1[i] = fmaf(d1, we_r[i], pre1[i]);
                    }
                    emit(sm->st2[w], sm->vqa2[jj], pre0, pre1, g, tg);
                }
            }
        }

        // ---- block reduce warp-private accumulators (once per ii0 group) ----
        __syncthreads();
        {
            int r = t >> 4, cq = (t & 15) * 4;
            float4 s4 = make_float4(0.f,0.f,0.f,0.f);
            #pragma unroll
            for (int ww=0; ww<8; ww++) {
                float4 v = *reinterpret_cast<float4*>(&sm->st[ww][r][cq]);
                s4.x += v.x; s4.y += v.y; s4.z += v.z; s4.w += v.w;
            }
            float4* d4 = reinterpret_cast<float4*>(&sm->svp[ii0+r][cq]);
            float4 o = *d4;
            o.x += s4.x; o.y += s4.y; o.z += s4.z; o.w += s4.w;
            *d4 = o;
            if (!diag) {
                float4 s5 = make_float4(0.f,0.f,0.f,0.f);
                #pragma unroll
                for (int ww=0; ww<8; ww++) {
                    float4 v = *reinterpret_cast<float4*>(&sm->st2[ww][r][cq]);
                    s5.x += v.x; s5.y += v.y; s5.z += v.z; s5.w += v.w;
                }
                float4* d5 = reinterpret_cast<float4*>(&sm->svq2[ii0+r][cq]);
                float4 o2 = *d5;
                o2.x += s5.x; o2.y += s5.y; o2.z += s5.z; o2.w += s5.w;
                *d5 = o2;
            }
        }
        __syncthreads();
    }

    // ---- flush ----
    for (int idx=t; idx<DD*DD; idx+=256) {
        int rr = idx>>6, ch = idx&63;
        atomicAdd(&d_vecp[(i0+rr)*DD + ch], sm->svp[rr][ch]);
        atomicAdd(&d_vecq[(j0+rr)*DD + ch], sm->vqa[rr][ch]);
        if (!diag) {
            atomicAdd(&d_vecq[(i0+rr)*DD + ch], sm->svq2[rr][ch]);
            atomicAdd(&d_vecp[(j0+rr)*DD + ch], sm->vqa2[rr][ch]);
        }
    }
}

// ------------------------- phase C ------------------------------------------
__global__ void k_prec(const float* __restrict__ gW) {
    __shared__ float s_v[DD];
    int i = blockIdx.x, c = threadIdx.x;
    int which = blockIdx.y;
    const float* src = which ? d_vecq : d_vecp;
    const float* w   = gW + (which ? 129 : 65)*DD;
    float*       dst = which ? d_VQ : d_VP;
    s_v[c] = src[i*DD + c];
    __syncthreads();
    float acc = 0.f;
    #pragma unroll 8
    for (int k=0; k<DD; k++) acc = fmaf(s_v[k], w[k*DD+c], acc);
    dst[i*DD + c] = acc;
}

__global__ void k_gpairs(const int* __restrict__ pos, const float* __restrict__ gW,
                         const float* __restrict__ gb, const float* __restrict__ lW,
                         const float* __restrict__ lb, float* __restrict__ out) {
    __shared__ float sgw[DD+1][DD];
    __shared__ float sgb[DD], slw[DD];
    int t = threadIdx.x;
    for (int idx=t; idx<(DD+1)*DD; idx+=256) sgw[idx>>6][idx&63] = gW[idx];
    if (t < DD) { sgb[t] = gb[t]; slw[t] = lW[t]; }
    __syncthreads();

    int gt = blockIdx.x*256 + t;
    int p = gt >> 5, lane = gt & 31;
    if (p >= NP) return;
    int i = pos[2*p], j = pos[2*p+1];
    int c0 = lane, c1 = lane + 32;
    const float* hi = d_h + i*DD;
    const float* hj = d_h + j*DD;

    float g0 = 0.f, g1 = 0.f;
    #pragma unroll 8
    for (int k=0; k<DD; k++) {
        float a = hi[k]*hj[k];
        g0 = fmaf(a, sgw[k][c0], g0);
        g1 = fmaf(a, sgw[k][c1], g1);
    }
    unsigned bij = (unsigned)i*NN + (unsigned)j;
    unsigned bji = (unsigned)j*NN + (unsigned)i;
    float eij = ((d_bitmap[bij>>5] >> (bij & 31u)) & 1u) ? 1.f : 0.f;
    float eji = ((d_bitmap[bji>>5] >> (bji & 31u)) & 1u) ? 1.f : 0.f;

    float aA0 = g0 + sgb[c0] + d_VP[i*DD+c0] + d_VQ[j*DD+c0] + eij*sgw[DD][c0];
    float aA1 = g1 + sgb[c1] + d_VP[i*DD+c1] + d_VQ[j*DD+c1] + eij*sgw[DD][c1];
    float aB0 = g0 + sgb[c0] + d_VP[j*DD+c0] + d_VQ[i*DD+c0] + eji*sgw[DD][c0];
    float aB1 = g1 + sgb[c1] + d_VP[j*DD+c1] + d_VQ[i*DD+c1] + eji*sgw[DD][c1];

    float s = aA0 + aA1;
    #pragma unroll
    for (int o=16; o>=1; o>>=1) s += __shfl_xor_sync(0xffffffffu, s, o);
    float mA = s*(1.f/DD);
    float dA0 = aA0-mA, dA1 = aA1-mA;
    float v = dA0*dA0 + dA1*dA1;
    #pragma unroll
    for (int o=16; o>=1; o>>=1) v += __shfl_xor_sync(0xffffffffu, v, o);
    float rA = rsqrtf(v*(1.f/DD) + LNEPS);
    float GA0 = fmaxf(dA0*rA, 0.f), GA1 = fmaxf(dA1*rA, 0.f);

    s = aB0 + aB1;
    #pragma unroll
    for (int o=16; o>=1; o>>=1) s += __shfl_xor_sync(0xffffffffu, s, o);
    float mB = s*(1.f/DD);
    float dB0 = aB0-mB, dB1 = aB1-mB;
    v = dB0*dB0 + dB1*dB1;
    #pragma unroll
    for (int o=16; o>=1; o>>=1) v += __shfl_xor_sync(0xffffffffu, v, o);
    float rB = rsqrtf(v*(1.f/DD) + LNEPS);
    float GB0 = fmaxf(dB0*rB, 0.f), GB1 = fmaxf(dB1*rB, 0.f);

    float o0 = GA0*GB0*slw[c0] + GA1*GB1*slw[c1];
    #pragma unroll
    for (int o=16; o>=1; o>>=1) o0 += __shfl_xor_sync(0xffffffffu, o0, o);
    if (lane == 0) out[p] = o0 + lb[0];
}

// ------------------------- launch -------------------------------------------
extern "C" void kernel_launch(void* const* d_in, const int* in_sizes, int n_in,
                              void* d_out, int out_size) {
    const int*   x   = (const int*)d_in[0];
    const int*   ei  = (const int*)d_in[1];
    const int*   pos = (const int*)d_in[2];
    const float* emb = (const float*)d_in[3];
    const float* sWl = (const float*)d_in[4];
    const float* sbl = (const float*)d_in[5];
    const float* sWr = (const float*)d_in[6];
    const float* hW  = (const float*)d_in[7];
    const float* hb  = (const float*)d_in[8];
    const float* gW  = (const float*)d_in[9];
    const float* gb  = (const float*)d_in[10];
    const float* lW  = (const float*)d_in[11];
    const float* lb  = (const float*)d_in[12];
    float* out = (float*)d_out;

    cudaFuncSetAttribute(k_pair, cudaFuncAttributeMaxDynamicSharedMemorySize,
                         (int)sizeof(PairSmem));

    k_init<<<256, 256>>>(x, emb);
    k_scat0<<<NE*DD/256, 256>>>(ei);
    k_sage<<<NN, DD>>>(sWl, sbl, sWr, 0);
    k_scatter<<<NE*DD/256, 256>>>(ei);
    k_sage<<<NN, DD>>>(sWl, sbl, sWr, 1);
    k_pair<<<136, 256, sizeof(PairSmem)>>>(hW, hb);
    k_prec<<<dim3(NN,2), DD>>>(gW);
    k_gpairs<<<(NP*32)/256, 256>>>(pos, gW, gb, lW, lb, out);
}

// round 9
// speedup vs baseline: 4.3536x; 1.1376x over previous
#include <cuda_runtime.h>
#include <cstdint>

#define NN 1024
#define DD 64
#define NE 16384
#define NP 8192
#define LNEPS 1e-5f

// ------------------------- helpers ------------------------------------------
__device__ __forceinline__ uint32_t cvt_tf32(float f) {
    uint32_t u; asm("cvt.rna.tf32.f32 %0, %1;" : "=r"(u) : "f"(f)); return u;
}
__device__ __forceinline__ void mma_tf32(float* d, uint32_t a0, uint32_t a1,
                                         uint32_t a2, uint32_t a3,
                                         uint32_t b0, uint32_t b1) {
    asm volatile(
        "mma.sync.aligned.m16n8k8.row.col.f32.tf32.tf32.f32 "
        "{%0,%1,%2,%3}, {%4,%5,%6,%7}, {%8,%9}, {%0,%1,%2,%3};"
        : "+f"(d[0]), "+f"(d[1]), "+f"(d[2]), "+f"(d[3])
        : "r"(a0), "r"(a1), "r"(a2), "r"(a3), "r"(b0), "r"(b1));
}

// ------------------------- scratch (device globals) -------------------------
__device__ float    d_h[NN*DD];
__device__ float    d_hn[NN*DD];
__device__ float    d_aggr[NN*DD];
__device__ float    d_deg[NN];
__device__ unsigned d_bitmap[NN*NN/32];
__device__ float    d_vecp[NN*DD];
__device__ float    d_vecq[NN*DD];
__device__ float    d_VP[NN*DD];
__device__ float    d_VQ[NN*DD];

// ------------------------- phase A ------------------------------------------
__global__ void k_init(const int* __restrict__ x, const float* __restrict__ emb) {
    int t  = blockIdx.x*blockDim.x + threadIdx.x;
    int st = gridDim.x*blockDim.x;
    for (int i=t; i<NN*NN/32; i+=st) d_bitmap[i] = 0u;
    for (int i=t; i<NN;       i+=st) d_deg[i]    = 0.f;
    for (int i=t; i<NN*DD;    i+=st) {
        d_vecp[i]=0.f; d_vecq[i]=0.f; d_aggr[i]=0.f;
        d_h[i] = emb[x[i>>6]*DD + (i&63)];
    }
}

__global__ void k_scat0(const int* __restrict__ ei) {
    int t = blockIdx.x*blockDim.x + threadIdx.x;
    if (t < NE*DD) {
        int e = t>>6, c = t&63;
        int s = ei[e], d = ei[NE+e];
        atomicAdd(&d_aggr[d*DD + c], d_h[s*DD + c]);
        if (c == 0) {
            atomicAdd(&d_deg[d], 1.f);
            unsigned idx = (unsigned)s*NN + (unsigned)d;
            atomicOr(&d_bitmap[idx>>5], 1u << (idx & 31u));
        }
    }
}

__global__ void k_scatter(const int* __restrict__ ei) {
    int t = blockIdx.x*blockDim.x + threadIdx.x;
    if (t < NE*DD) {
        int e = t>>6, c = t&63;
        atomicAdd(&d_aggr[ei[NE+e]*DD + c], d_hn[ei[e]*DD + c]);
    }
}

__global__ void k_sage(const float* __restrict__ Wl, const float* __restrict__ bl,
                       const float* __restrict__ Wr, int layer) {
    __shared__ float s_in[DD], s_ag[DD], s_red[DD];
    int i = blockIdx.x, c = threadIdx.x;
    const float* hs = layer ? d_hn : d_h;
    float*       hd = layer ? d_h  : d_hn;
    float dg = fmaxf(d_deg[i], 1.f);
    s_in[c] = hs[i*DD+c];
    s_ag[c] = d_aggr[i*DD+c] / dg;
    d_aggr[i*DD+c] = 0.f;
    __syncthreads();
    const float* wl = Wl + layer*DD*DD;
    const float* wr = Wr + layer*DD*DD;
    float acc = bl[layer*DD + c];
    #pragma unroll 8
    for (int k=0; k<DD; k++)
        acc = fmaf(s_ag[k], wl[k*DD+c], fmaf(s_in[k], wr[k*DD+c], acc));
    s_red[c] = acc;
    __syncthreads();
    float m = 0.f;
    #pragma unroll 8
    for (int k=0; k<DD; k++) m += s_red[k];
    m *= (1.f/DD);
    float v = 0.f;
    #pragma unroll 8
    for (int k=0; k<DD; k++) { float dd0 = s_red[k]-m; v = fmaf(dd0, dd0, v); }
    v *= (1.f/DD);
    hd[i*DD+c] = (acc - m) * rsqrtf(v + LNEPS);
}

// ------------------------- phase B: mma.sync tf32 pair kernel ---------------
struct PairSmem {
    float    hi_s[64][68];
    float    hj_s[64][68];
    float    wtf[64][72];      // W tf32-rounded [k][n]
    float    st[8][16][68];    // warp-private accum: normal B rows (ii-local)
    float    st2[8][16][68];   // warp-private accum: mirror CORRECTIONS
    float    vqa[64][68];      // vq by jj (normal)
    float    vqa2[64][68];     // vecp corrections by jj (mirror delta)
    float    svp[64][68];      // vp by ii (normal)
    float    svq2[64][68];     // vecq corrections by ii (mirror delta)
    float    hwe[64], hbias[64];
    unsigned bm0[64][2], bm1[64][2];
};

// single-pass LN stats: m = E[x], r = 1/sqrt(E[x^2]-m^2+eps). Two independent
// 2-deep shfl chains (vs serial 4-deep in the two-pass version).
__device__ __forceinline__ void ln16s(const float* pre, float& m, float& r) {
    float s1 = 0.f, s2 = 0.f;
    #pragma unroll
    for (int i=0;i<16;i++) { s1 += pre[i]; s2 = fmaf(pre[i], pre[i], s2); }
    s1 += __shfl_xor_sync(0xffffffffu, s1, 1);
    s2 += __shfl_xor_sync(0xffffffffu, s2, 1);
    s1 += __shfl_xor_sync(0xffffffffu, s1, 2);
    s2 += __shfl_xor_sync(0xffffffffu, s2, 2);
    m = s1 * (1.f/DD);
    r = rsqrtf(fmaf(-m, m, s2*(1.f/DD)) + LNEPS);
}

// normal emission: accumulates b into stacc (by ii) and vqrow (by jj).
// Returns LN stats so the mirror-delta path can recompute b_normal.
__device__ __forceinline__ void emit(float (*stacc)[68], float* vqrow,
                                     const float* pre0, const float* pre1,
                                     int g, int tg,
                                     float& m0, float& r0, float& m1, float& r1) {
    ln16s(pre0, m0, r0);
    ln16s(pre1, m1, r1);
    float vs[16];
    #pragma unroll
    for (int nt=0; nt<8; nt++) {
        int i0i = 2*nt, i1i = i0i+1;
        float b00 = fmaxf((pre0[i0i]-m0)*r0, 0.f);
        float b01 = fmaxf((pre0[i1i]-m0)*r0, 0.f);
        float b10 = fmaxf((pre1[i0i]-m1)*r1, 0.f);
        float b11 = fmaxf((pre1[i1i]-m1)*r1, 0.f);
        vs[i0i] = b00 + b10; vs[i1i] = b01 + b11;
        int ch0 = nt*8 + 2*tg;
        float2* pA = reinterpret_cast<float2*>(&stacc[g][ch0]);
        float2 a = *pA; a.x += b00; a.y += b01; *pA = a;
        float2* pB = reinterpret_cast<float2*>(&stacc[g+8][ch0]);
        float2 b = *pB; b.x += b10; b.y += b11; *pB = b;
    }
    #pragma unroll
    for (int msk=4; msk<=16; msk<<=1) {
        #pragma unroll
        for (int i=0;i<16;i++) vs[i] += __shfl_xor_sync(0xffffffffu, vs[i], msk);
    }
    if (g == 0) {
        #pragma unroll
        for (int nt=0; nt<8; nt++) {
            int ch0 = nt*8 + 2*tg;
            float2* p = reinterpret_cast<float2*>(&vqrow[ch0]);
            float2 v = *p; v.x += vs[2*nt]; v.y += vs[2*nt+1]; *p = v;
        }
    }
}

// mirror delta emission: accumulates (b_mirror - b_normal) into correction
// buffers. Rows with no edge difference contribute bitwise-zero deltas.
__device__ __forceinline__ void emit_delta(float (*stacc)[68], float* vqrow,
                                           const float* pre0, const float* pre1,
                                           float d0, float d1,
                                           float m0, float r0, float m1, float r1,
                                           const float* we_r, int g, int tg) {
    float pm0[16], pm1[16];
    #pragma unroll
    for (int i=0;i<16;i++) {
        pm0[i] = fmaf(d0, we_r[i], pre0[i]);
        pm1[i] = fmaf(d1, we_r[i], pre1[i]);
    }
    float mm0, rr0, mm1, rr1;
    ln16s(pm0, mm0, rr0);
    ln16s(pm1, mm1, rr1);
    float vs[16];
    #pragma unroll
    for (int nt=0; nt<8; nt++) {
        int i0i = 2*nt, i1i = i0i+1;
        float dl00 = fmaxf((pm0[i0i]-mm0)*rr0,0.f) - fmaxf((pre0[i0i]-m0)*r0,0.f);
        float dl01 = fmaxf((pm0[i1i]-mm0)*rr0,0.f) - fmaxf((pre0[i1i]-m0)*r0,0.f);
        float dl10 = fmaxf((pm1[i0i]-mm1)*rr1,0.f) - fmaxf((pre1[i0i]-m1)*r1,0.f);
        float dl11 = fmaxf((pm1[i1i]-mm1)*rr1,0.f) - fmaxf((pre1[i1i]-m1)*r1,0.f);
        vs[i0i] = dl00 + dl10; vs[i1i] = dl01 + dl11;
        int ch0 = nt*8 + 2*tg;
        float2* pA = reinterpret_cast<float2*>(&stacc[g][ch0]);
        float2 a = *pA; a.x += dl00; a.y += dl01; *pA = a;
        float2* pB = reinterpret_cast<float2*>(&stacc[g+8][ch0]);
        float2 b = *pB; b.x += dl10; b.y += dl11; *pB = b;
    }
    #pragma unroll
    for (int msk=4; msk<=16; msk<<=1) {
        #pragma unroll
        for (int i=0;i<16;i++) vs[i] += __shfl_xor_sync(0xffffffffu, vs[i], msk);
    }
    if (g == 0) {
        #pragma unroll
        for (int nt=0; nt<8; nt++) {
            int ch0 = nt*8 + 2*tg;
            float2* p = reinterpret_cast<float2*>(&vqrow[ch0]);
            float2 v = *p; v.x += vs[2*nt]; v.y += vs[2*nt+1]; *p = v;
        }
    }
}

__global__ void __launch_bounds__(256,1) k_pair(const float* __restrict__ hW,
                                                const float* __restrict__ hb) {
    extern __shared__ char smraw[];
    PairSmem* sm = reinterpret_cast<PairSmem*>(smraw);
    int t = threadIdx.x;
    int lane = t & 31, w = t >> 5;
    int g = lane >> 2, tg = lane & 3;

    int bi = 0, rem = blockIdx.x;
    while (rem >= 16 - bi) { rem -= 16 - bi; bi++; }
    int bj = bi + rem;
    int i0 = bi*64, j0 = bj*64;
    bool diag = (bi == bj);

    for (int idx=t; idx<DD*DD; idx+=256) {
        int r = idx>>6, k = idx&63;
        sm->hi_s[r][k] = d_h[(i0+r)*DD + k];
        sm->hj_s[r][k] = d_h[(j0+r)*DD + k];
        sm->wtf[r][k]  = __uint_as_float(cvt_tf32(hW[r*DD + k]));
    }
    for (int idx=t; idx<DD*68; idx+=256) {
        sm->vqa [idx/68][idx%68] = 0.f;
        sm->vqa2[idx/68][idx%68] = 0.f;
        sm->svp [idx/68][idx%68] = 0.f;
        sm->svq2[idx/68][idx%68] = 0.f;
    }
    if (t < DD) { sm->hwe[t] = hW[DD*DD + t]; sm->hbias[t] = hb[t]; }
    if (t < 128) {
        int r = t>>1, wd = t&1;
        sm->bm0[r][wd] = d_bitmap[((unsigned)(i0+r)*NN + (unsigned)j0)/32 + wd];
        sm->bm1[r][wd] = d_bitmap[((unsigned)(j0+r)*NN + (unsigned)i0)/32 + wd];
    }
    __syncthreads();

    float hb_r[16], we_r[16];
    #pragma unroll
    for (int i=0;i<16;i++) {
        int ch = (i>>1)*8 + 2*tg + (i&1);
        hb_r[i] = sm->hbias[ch];
        we_r[i] = sm->hwe[ch];
    }

    for (int i0b=0; i0b<4; i0b++) {
        int ii0 = i0b*16;
        {
            float4 z = make_float4(0.f,0.f,0.f,0.f);
            float* stf  = &sm->st [w][0][0];
            float* st2f = &sm->st2[w][0][0];
            for (int idx=lane; idx<16*17; idx+=32) {
                *reinterpret_cast<float4*>(stf  + idx*4) = z;
                *reinterpret_cast<float4*>(st2f + idx*4) = z;
            }
        }
        __syncwarp();

        for (int q=0; q<4; q++) {
            int jjA = w*8 + 2*q, jjB = jjA + 1;

            float accA[8][4], accB[8][4];
            #pragma unroll
            for (int nt=0; nt<8; nt++) {
                accA[nt][0]=accA[nt][1]=accA[nt][2]=accA[nt][3]=0.f;
                accB[nt][0]=accB[nt][1]=accB[nt][2]=accB[nt][3]=0.f;
            }

            #pragma unroll
            for (int kt=0; kt<8; kt++) {
                int k0 = kt*8 + tg, k1 = k0 + 4;
                float hjA0 = sm->hj_s[jjA][k0], hjA1 = sm->hj_s[jjA][k1];
                float hjB0 = sm->hj_s[jjB][k0], hjB1 = sm->hj_s[jjB][k1];
                float hi00 = sm->hi_s[ii0+g][k0],   hi01 = sm->hi_s[ii0+g][k1];
                float hi80 = sm->hi_s[ii0+g+8][k0], hi81 = sm->hi_s[ii0+g+8][k1];
                uint32_t aA0 = cvt_tf32(hi00*hjA0);
                uint32_t aA1 = cvt_tf32(hi80*hjA0);
                uint32_t aA2 = cvt_tf32(hi01*hjA1);
                uint32_t aA3 = cvt_tf32(hi81*hjA1);
                uint32_t aB0 = cvt_tf32(hi00*hjB0);
                uint32_t aB1 = cvt_tf32(hi80*hjB0);
                uint32_t aB2 = cvt_tf32(hi01*hjB1);
                uint32_t aB3 = cvt_tf32(hi81*hjB1);
                #pragma unroll
                for (int nt=0; nt<8; nt++) {
                    uint32_t b0 = __float_as_uint(sm->wtf[k0][nt*8+g]);
                    uint32_t b1 = __float_as_uint(sm->wtf[k1][nt*8+g]);
                    mma_tf32(accA[nt], aA0, aA1, aA2, aA3, b0, b1);
                    mma_tf32(accB[nt], aB0, aB1, aB2, aB3, b0, b1);
                }
            }

            #pragma unroll
            for (int half=0; half<2; half++) {
                int jj = half ? jjB : jjA;
                float (*acc)[4] = half ? accB : accA;
                float e_g  = ((sm->bm0[ii0+g  ][jj>>5] >> (jj&31)) & 1u) ? 1.f : 0.f;
                float e_g8 = ((sm->bm0[ii0+g+8][jj>>5] >> (jj&31)) & 1u) ? 1.f : 0.f;
                float pre0[16], pre1[16];
                #pragma unroll
                for (int nt=0; nt<8; nt++) {
                    #pragma unroll
                    for (int hf=0; hf<2; hf++) {
                        int i = 2*nt + hf;
                        pre0[i] = acc[nt][hf]   + hb_r[i] + e_g *we_r[i];
                        pre1[i] = acc[nt][2+hf] + hb_r[i] + e_g8*we_r[i];
                    }
                }
                float m0, r0, m1, r1;
                emit(sm->st[w], sm->vqa[jj], pre0, pre1, g, tg, m0, r0, m1, r1);

                if (!diag) {
                    float ep_g  = ((sm->bm1[jj][(ii0+g  )>>5] >> ((ii0+g  )&31)) & 1u) ? 1.f : 0.f;
                    float ep_g8 = ((sm->bm1[jj][(ii0+g+8)>>5] >> ((ii0+g+8)&31)) & 1u) ? 1.f : 0.f;
                    float dd0 = ep_g - e_g, dd1 = ep_g8 - e_g8;
                    bool nd = (dd0 != 0.f) || (dd1 != 0.f);
                    if (__any_sync(0xffffffffu, nd)) {
                        emit_delta(sm->st2[w], sm->vqa2[jj], pre0, pre1,
                                   dd0, dd1, m0, r0, m1, r1, we_r, g, tg);
                    }
                }
            }
        }

        // ---- block reduce warp-private accumulators (once per ii0 group) ----
        __syncthreads();
        {
            int r = t >> 4, cq = (t & 15) * 4;
            float4 s4 = make_float4(0.f,0.f,0.f,0.f);
            #pragma unroll
            for (int ww=0; ww<8; ww++) {
                float4 v = *reinterpret_cast<float4*>(&sm->st[ww][r][cq]);
                s4.x += v.x; s4.y += v.y; s4.z += v.z; s4.w += v.w;
            }
            float4* d4 = reinterpret_cast<float4*>(&sm->svp[ii0+r][cq]);
            float4 o = *d4;
            o.x += s4.x; o.y += s4.y; o.z += s4.z; o.w += s4.w;
            *d4 = o;
            if (!diag) {
                float4 s5 = make_float4(0.f,0.f,0.f,0.f);
                #pragma unroll
                for (int ww=0; ww<8; ww++) {
                    float4 v = *reinterpret_cast<float4*>(&sm->st2[ww][r][cq]);
                    s5.x += v.x; s5.y += v.y; s5.z += v.z; s5.w += v.w;
                }
                float4* d5 = reinterpret_cast<float4*>(&sm->svq2[ii0+r][cq]);
                float4 o2 = *d5;
                o2.x += s5.x; o2.y += s5.y; o2.z += s5.z; o2.w += s5.w;
                *d5 = o2;
            }
        }
        __syncthreads();
    }

    // ---- flush: mirror outputs = normal accumulators + sparse corrections ----
    for (int idx=t; idx<DD*DD; idx+=256) {
        int rr = idx>>6, ch = idx&63;
        float rowsum = sm->svp[rr][ch];   // normal by-ii row sums
        float colsum = sm->vqa[rr][ch];   // normal by-jj col sums
        atomicAdd(&d_vecp[(i0+rr)*DD + ch], rowsum);
        atomicAdd(&d_vecq[(j0+rr)*DD + ch], colsum);
        if (!diag) {
            atomicAdd(&d_vecq[(i0+rr)*DD + ch], rowsum + sm->svq2[rr][ch]);
            atomicAdd(&d_vecp[(j0+rr)*DD + ch], colsum + sm->vqa2[rr][ch]);
        }
    }
}

// ------------------------- phase C ------------------------------------------
__global__ void k_prec(const float* __restrict__ gW) {
    __shared__ float s_v[DD];
    int i = blockIdx.x, c = threadIdx.x;
    int which = blockIdx.y;
    const float* src = which ? d_vecq : d_vecp;
    const float* w   = gW + (which ? 129 : 65)*DD;
    float*       dst = which ? d_VQ : d_VP;
    s_v[c] = src[i*DD + c];
    __syncthreads();
    float acc = 0.f;
    #pragma unroll 8
    for (int k=0; k<DD; k++) acc = fmaf(s_v[k], w[k*DD+c], acc);
    dst[i*DD + c] = acc;
}

__global__ void k_gpairs(const int* __restrict__ pos, const float* __restrict__ gW,
                         const float* __restrict__ gb, const float* __restrict__ lW,
                         const float* __restrict__ lb, float* __restrict__ out) {
    __shared__ float sgw[DD+1][DD];
    __shared__ float sgb[DD], slw[DD];
    int t = threadIdx.x;
    for (int idx=t; idx<(DD+1)*DD; idx+=256) sgw[idx>>6][idx&63] = gW[idx];
    if (t < DD) { sgb[t] = gb[t]; slw[t] = lW[t]; }
    __syncthreads();

    int gt = blockIdx.x*256 + t;
    int p = gt >> 5, lane = gt & 31;
    if (p >= NP) return;
    int i = pos[2*p], j = pos[2*p+1];
    int c0 = lane, c1 = lane + 32;
    const float* hi = d_h + i*DD;
    const float* hj = d_h + j*DD;

    float g0 = 0.f, g1 = 0.f;
    #pragma unroll 8
    for (int k=0; k<DD; k++) {
        float a = hi[k]*hj[k];
        g0 = fmaf(a, sgw[k][c0], g0);
        g1 = fmaf(a, sgw[k][c1], g1);
    }
    unsigned bij = (unsigned)i*NN + (unsigned)j;
    unsigned bji = (unsigned)j*NN + (unsigned)i;
    float eij = ((d_bitmap[bij>>5] >> (bij & 31u)) & 1u) ? 1.f : 0.f;
    float eji = ((d_bitmap[bji>>5] >> (bji & 31u)) & 1u) ? 1.f : 0.f;

    float aA0 = g0 + sgb[c0] + d_VP[i*DD+c0] + d_VQ[j*DD+c0] + eij*sgw[DD][c0];
    float aA1 = g1 + sgb[c1] + d_VP[i*DD+c1] + d_VQ[j*DD+c1] + eij*sgw[DD][c1];
    float aB0 = g0 + sgb[c0] + d_VP[j*DD+c0] + d_VQ[i*DD+c0] + eji*sgw[DD][c0];
    float aB1 = g1 + sgb[c1] + d_VP[j*DD+c1] + d_VQ[i*DD+c1] + eji*sgw[DD][c1];

    // LN A and LN B, single-pass (mean + sumsq reduced in parallel chains)
    float sA = aA0 + aA1, qA = aA0*aA0 + aA1*aA1;
    float sB = aB0 + aB1, qB = aB0*aB0 + aB1*aB1;
    #pragma unroll
    for (int o=16; o>=1; o>>=1) {
        sA += __shfl_xor_sync(0xffffffffu, sA, o);
        qA += __shfl_xor_sync(0xffffffffu, qA, o);
        sB += __shfl_xor_sync(0xffffffffu, sB, o);
        qB += __shfl_xor_sync(0xffffffffu, qB, o);
    }
    float mA = sA*(1.f/DD);
    float rA = rsqrtf(fmaf(-mA, mA, qA*(1.f/DD)) + LNEPS);
    float mB = sB*(1.f/DD);
    float rB = rsqrtf(fmaf(-mB, mB, qB*(1.f/DD)) + LNEPS);
    float GA0 = fmaxf((aA0-mA)*rA, 0.f), GA1 = fmaxf((aA1-mA)*rA, 0.f);
    float GB0 = fmaxf((aB0-mB)*rB, 0.f), GB1 = fmaxf((aB1-mB)*rB, 0.f);

    float o0 = GA0*GB0*slw[c0] + GA1*GB1*slw[c1];
    #pragma unroll
    for (int o=16; o>=1; o>>=1) o0 += __shfl_xor_sync(0xffffffffu, o0, o);
    if (lane == 0) out[p] = o0 + lb[0];
}

// ------------------------- launch -------------------------------------------
extern "C" void kernel_launch(void* const* d_in, const int* in_sizes, int n_in,
                              void* d_out, int out_size) {
    const int*   x   = (const int*)d_in[0];
    const int*   ei  = (const int*)d_in[1];
    const int*   pos = (const int*)d_in[2];
    const float* emb = (const float*)d_in[3];
    const float* sWl = (const float*)d_in[4];
    const float* sbl = (const float*)d_in[5];
    const float* sWr = (const float*)d_in[6];
    const float* hW  = (const float*)d_in[7];
    const float* hb  = (const float*)d_in[8];
    const float* gW  = (const float*)d_in[9];
    const float* gb  = (const float*)d_in[10];
    const float* lW  = (const float*)d_in[11];
    const float* lb  = (const float*)d_in[12];
    float* out = (float*)d_out;

    cudaFuncSetAttribute(k_pair, cudaFuncAttributeMaxDynamicSharedMemorySize,
                         (int)sizeof(PairSmem));

    k_init<<<256, 256>>>(x, emb);
    k_scat0<<<NE*DD/256, 256>>>(ei);
    k_sage<<<NN, DD>>>(sWl, sbl, sWr, 0);
    k_scatter<<<NE*DD/256, 256>>>(ei);
    k_sage<<<NN, DD>>>(sWl, sbl, sWr, 1);
    k_pair<<<136, 256, sizeof(PairSmem)>>>(hW, hb);
    k_prec<<<dim3(NN,2), DD>>>(gW);
    k_gpairs<<<(NP*32)/256, 256>>>(pos, gW, gb, lW, lb, out);
}

// round 10
// speedup vs baseline: 4.6910x; 1.0775x over previous
#include <cuda_runtime.h>
#include <cstdint>

#define NN 1024
#define DD 64
#define NE 16384
#define NP 8192
#define LNEPS 1e-5f

// ------------------------- helpers ------------------------------------------
__device__ __forceinline__ uint32_t cvt_tf32(float f) {
    uint32_t u; asm("cvt.rna.tf32.f32 %0, %1;" : "=r"(u) : "f"(f)); return u;
}
__device__ __forceinline__ void mma_tf32(float* d, uint32_t a0, uint32_t a1,
                                         uint32_t a2, uint32_t a3,
                                         uint32_t b0, uint32_t b1) {
    asm volatile(
        "mma.sync.aligned.m16n8k8.row.col.f32.tf32.tf32.f32 "
        "{%0,%1,%2,%3}, {%4,%5,%6,%7}, {%8,%9}, {%0,%1,%2,%3};"
        : "+f"(d[0]), "+f"(d[1]), "+f"(d[2]), "+f"(d[3])
        : "r"(a0), "r"(a1), "r"(a2), "r"(a3), "r"(b0), "r"(b1));
}
__device__ __forceinline__ void red2(float* gptr, float x, float y) {
    asm volatile("red.global.add.v2.f32 [%0], {%1,%2};"
                 :: "l"(gptr), "f"(x), "f"(y) : "memory");
}

// ------------------------- scratch (device globals) -------------------------
__device__ float    d_h[NN*DD];
__device__ float    d_hn[NN*DD];
__device__ float    d_aggr[NN*DD];
__device__ float    d_deg[NN];
__device__ unsigned d_bitmap[NN*NN/32];
__device__ float    d_vecp[NN*DD];
__device__ float    d_vecq[NN*DD];
__device__ float    d_VP[NN*DD];
__device__ float    d_VQ[NN*DD];

// ------------------------- phase A ------------------------------------------
__global__ void k_init(const int* __restrict__ x, const float* __restrict__ emb) {
    int t  = blockIdx.x*blockDim.x + threadIdx.x;
    int st = gridDim.x*blockDim.x;
    for (int i=t; i<NN*NN/32; i+=st) d_bitmap[i] = 0u;
    for (int i=t; i<NN;       i+=st) d_deg[i]    = 0.f;
    for (int i=t; i<NN*DD;    i+=st) {
        d_vecp[i]=0.f; d_vecq[i]=0.f; d_aggr[i]=0.f;
        d_h[i] = emb[x[i>>6]*DD + (i&63)];
    }
}

__global__ void k_scat0(const int* __restrict__ ei) {
    int t = blockIdx.x*blockDim.x + threadIdx.x;
    if (t < NE*32) {
        int e = t>>5, cq = t&31;
        int s = ei[e], d = ei[NE+e];
        float2 v = *reinterpret_cast<const float2*>(&d_h[s*DD + cq*2]);
        red2(&d_aggr[d*DD + cq*2], v.x, v.y);
        if (cq == 0) {
            atomicAdd(&d_deg[d], 1.f);
            unsigned idx = (unsigned)s*NN + (unsigned)d;
            atomicOr(&d_bitmap[idx>>5], 1u << (idx & 31u));
        }
    }
}

__global__ void k_scatter(const int* __restrict__ ei) {
    int t = blockIdx.x*blockDim.x + threadIdx.x;
    if (t < NE*32) {
        int e = t>>5, cq = t&31;
        float2 v = *reinterpret_cast<const float2*>(&d_hn[ei[e]*DD + cq*2]);
        red2(&d_aggr[ei[NE+e]*DD + cq*2], v.x, v.y);
    }
}

__global__ void k_sage(const float* __restrict__ Wl, const float* __restrict__ bl,
                       const float* __restrict__ Wr, int layer) {
    __shared__ float s_in[DD], s_ag[DD], s_red[DD];
    int i = blockIdx.x, c = threadIdx.x;
    const float* hs = layer ? d_hn : d_h;
    float*       hd = layer ? d_h  : d_hn;
    float dg = fmaxf(d_deg[i], 1.f);
    s_in[c] = hs[i*DD+c];
    s_ag[c] = d_aggr[i*DD+c] / dg;
    d_aggr[i*DD+c] = 0.f;
    __syncthreads();
    const float* wl = Wl + layer*DD*DD;
    const float* wr = Wr + layer*DD*DD;
    float acc = bl[layer*DD + c];
    #pragma unroll 8
    for (int k=0; k<DD; k++)
        acc = fmaf(s_ag[k], wl[k*DD+c], fmaf(s_in[k], wr[k*DD+c], acc));
    s_red[c] = acc;
    __syncthreads();
    float m = 0.f;
    #pragma unroll 8
    for (int k=0; k<DD; k++) m += s_red[k];
    m *= (1.f/DD);
    float v = 0.f;
    #pragma unroll 8
    for (int k=0; k<DD; k++) { float dd0 = s_red[k]-m; v = fmaf(dd0, dd0, v); }
    v *= (1.f/DD);
    hd[i*DD+c] = (acc - m) * rsqrtf(v + LNEPS);
}

// ------------------------- phase B: mma.sync tf32 pair kernel ---------------
struct PairSmem {
    float    hi_s[64][68];
    float    hj_s[64][68];
    float    wtf[64][72];      // W tf32-rounded [k][n]
    float    st[8][16][68];    // warp-private row sums (write-once per i0b)
    float    st2[8][16][68];   // warp-private mirror CORRECTIONS (RMW, sparse)
    float    vqa[64][68];      // vq by jj (normal)
    float    vqa2[64][68];     // vecp corrections by jj (mirror delta)
    float    svp[64][68];      // vp by ii (normal)
    float    svq2[64][68];     // vecq corrections by ii (mirror delta)
    float    hwe[64], hbias[64];
    unsigned bm0[64][2], bm1[64][2];
};

// single-pass LN stats
__device__ __forceinline__ void ln16s(const float* pre, float& m, float& r) {
    float s1 = 0.f, s2 = 0.f;
    #pragma unroll
    for (int i=0;i<16;i++) { s1 += pre[i]; s2 = fmaf(pre[i], pre[i], s2); }
    s1 += __shfl_xor_sync(0xffffffffu, s1, 1);
    s2 += __shfl_xor_sync(0xffffffffu, s2, 1);
    s1 += __shfl_xor_sync(0xffffffffu, s1, 2);
    s2 += __shfl_xor_sync(0xffffffffu, s2, 2);
    m = s1 * (1.f/DD);
    r = rsqrtf(fmaf(-m, m, s2*(1.f/DD)) + LNEPS);
}

// normal emission: row sums into rs registers (rs[0..15]=row g, rs[16..31]=g+8),
// col sums into vqrow via butterfly.
__device__ __forceinline__ void emit(float* rs, float* vqrow,
                                     const float* pre0, const float* pre1,
                                     int g, int tg,
                                     float& m0, float& r0, float& m1, float& r1) {
    ln16s(pre0, m0, r0);
    ln16s(pre1, m1, r1);
    float vs[16];
    #pragma unroll
    for (int nt=0; nt<8; nt++) {
        int i0i = 2*nt, i1i = i0i+1;
        float b00 = fmaxf((pre0[i0i]-m0)*r0, 0.f);
        float b01 = fmaxf((pre0[i1i]-m0)*r0, 0.f);
        float b10 = fmaxf((pre1[i0i]-m1)*r1, 0.f);
        float b11 = fmaxf((pre1[i1i]-m1)*r1, 0.f);
        vs[i0i] = b00 + b10; vs[i1i] = b01 + b11;
        rs[i0i]    += b00;  rs[i1i]    += b01;
        rs[16+i0i] += b10;  rs[16+i1i] += b11;
    }
    #pragma unroll
    for (int msk=4; msk<=16; msk<<=1) {
        #pragma unroll
        for (int i=0;i<16;i++) vs[i] += __shfl_xor_sync(0xffffffffu, vs[i], msk);
    }
    if (g == 0) {
        #pragma unroll
        for (int nt=0; nt<8; nt++) {
            int ch0 = nt*8 + 2*tg;
            float2* p = reinterpret_cast<float2*>(&vqrow[ch0]);
            float2 v = *p; v.x += vs[2*nt]; v.y += vs[2*nt+1]; *p = v;
        }
    }
}

// mirror delta emission: (b_mirror - b_normal) into correction buffers.
__device__ __forceinline__ void emit_delta(float (*stacc)[68], float* vqrow,
                                           const float* pre0, const float* pre1,
                                           float d0, float d1,
                                           float m0, float r0, float m1, float r1,
                                           const float* we_r, int g, int tg) {
    float pm0[16], pm1[16];
    #pragma unroll
    for (int i=0;i<16;i++) {
        pm0[i] = fmaf(d0, we_r[i], pre0[i]);
        pm1[i] = fmaf(d1, we_r[i], pre1[i]);
    }
    float mm0, rr0, mm1, rr1;
    ln16s(pm0, mm0, rr0);
    ln16s(pm1, mm1, rr1);
    float vs[16];
    #pragma unroll
    for (int nt=0; nt<8; nt++) {
        int i0i = 2*nt, i1i = i0i+1;
        float dl00 = fmaxf((pm0[i0i]-mm0)*rr0,0.f) - fmaxf((pre0[i0i]-m0)*r0,0.f);
        float dl01 = fmaxf((pm0[i1i]-mm0)*rr0,0.f) - fmaxf((pre0[i1i]-m0)*r0,0.f);
        float dl10 = fmaxf((pm1[i0i]-mm1)*rr1,0.f) - fmaxf((pre1[i0i]-m1)*r1,0.f);
        float dl11 = fmaxf((pm1[i1i]-mm1)*rr1,0.f) - fmaxf((pre1[i1i]-m1)*r1,0.f);
        vs[i0i] = dl00 + dl10; vs[i1i] = dl01 + dl11;
        int ch0 = nt*8 + 2*tg;
        float2* pA = reinterpret_cast<float2*>(&stacc[g][ch0]);
        float2 a = *pA; a.x += dl00; a.y += dl01; *pA = a;
        float2* pB = reinterpret_cast<float2*>(&stacc[g+8][ch0]);
        float2 b = *pB; b.x += dl10; b.y += dl11; *pB = b;
    }
    #pragma unroll
    for (int msk=4; msk<=16; msk<<=1) {
        #pragma unroll
        for (int i=0;i<16;i++) vs[i] += __shfl_xor_sync(0xffffffffu, vs[i], msk);
    }
    if (g == 0) {
        #pragma unroll
        for (int nt=0; nt<8; nt++) {
            int ch0 = nt*8 + 2*tg;
            float2* p = reinterpret_cast<float2*>(&vqrow[ch0]);
            float2 v = *p; v.x += vs[2*nt]; v.y += vs[2*nt+1]; *p = v;
        }
    }
}

__global__ void __launch_bounds__(256,1) k_pair(const float* __restrict__ hW,
                                                const float* __restrict__ hb) {
    extern __shared__ char smraw[];
    PairSmem* sm = reinterpret_cast<PairSmem*>(smraw);
    int t = threadIdx.x;
    int lane = t & 31, w = t >> 5;
    int g = lane >> 2, tg = lane & 3;

    int bi = 0, rem = blockIdx.x;
    while (rem >= 16 - bi) { rem -= 16 - bi; bi++; }
    int bj = bi + rem;
    int i0 = bi*64, j0 = bj*64;
    bool diag = (bi == bj);

    for (int idx=t; idx<DD*DD; idx+=256) {
        int r = idx>>6, k = idx&63;
        sm->hi_s[r][k] = d_h[(i0+r)*DD + k];
        sm->hj_s[r][k] = d_h[(j0+r)*DD + k];
        sm->wtf[r][k]  = __uint_as_float(cvt_tf32(hW[r*DD + k]));
    }
    for (int idx=t; idx<DD*68; idx+=256) {
        sm->vqa [idx/68][idx%68] = 0.f;
        sm->vqa2[idx/68][idx%68] = 0.f;
        sm->svp [idx/68][idx%68] = 0.f;
        sm->svq2[idx/68][idx%68] = 0.f;
    }
    if (t < DD) { sm->hwe[t] = hW[DD*DD + t]; sm->hbias[t] = hb[t]; }
    if (t < 128) {
        int r = t>>1, wd = t&1;
        sm->bm0[r][wd] = d_bitmap[((unsigned)(i0+r)*NN + (unsigned)j0)/32 + wd];
        sm->bm1[r][wd] = d_bitmap[((unsigned)(j0+r)*NN + (unsigned)i0)/32 + wd];
    }
    __syncthreads();

    float hb_r[16], we_r[16];
    #pragma unroll
    for (int i=0;i<16;i++) {
        int ch = (i>>1)*8 + 2*tg + (i&1);
        hb_r[i] = sm->hbias[ch];
        we_r[i] = sm->hwe[ch];
    }

    for (int i0b=0; i0b<4; i0b++) {
        int ii0 = i0b*16;
        // zero only st2 (st is write-once below); rs registers reset
        {
            float4 z = make_float4(0.f,0.f,0.f,0.f);
            float* st2f = &sm->st2[w][0][0];
            for (int idx=lane; idx<16*17; idx+=32)
                *reinterpret_cast<float4*>(st2f + idx*4) = z;
        }
        float rs[32];
        #pragma unroll
        for (int i=0;i<32;i++) rs[i] = 0.f;
        __syncwarp();

        for (int q=0; q<4; q++) {
            int jjA = w*8 + 2*q, jjB = jjA + 1;

            float accA[8][4], accB[8][4];
            #pragma unroll
            for (int nt=0; nt<8; nt++) {
                accA[nt][0]=accA[nt][1]=accA[nt][2]=accA[nt][3]=0.f;
                accB[nt][0]=accB[nt][1]=accB[nt][2]=accB[nt][3]=0.f;
            }

            #pragma unroll
            for (int kt=0; kt<8; kt++) {
                int k0 = kt*8 + tg, k1 = k0 + 4;
                float hjA0 = sm->hj_s[jjA][k0], hjA1 = sm->hj_s[jjA][k1];
                float hjB0 = sm->hj_s[jjB][k0], hjB1 = sm->hj_s[jjB][k1];
                float hi00 = sm->hi_s[ii0+g][k0],   hi01 = sm->hi_s[ii0+g][k1];
                float hi80 = sm->hi_s[ii0+g+8][k0], hi81 = sm->hi_s[ii0+g+8][k1];
                uint32_t aA0 = cvt_tf32(hi00*hjA0);
                uint32_t aA1 = cvt_tf32(hi80*hjA0);
                uint32_t aA2 = cvt_tf32(hi01*hjA1);
                uint32_t aA3 = cvt_tf32(hi81*hjA1);
                uint32_t aB0 = cvt_tf32(hi00*hjB0);
                uint32_t aB1 = cvt_tf32(hi80*hjB0);
                uint32_t aB2 = cvt_tf32(hi01*hjB1);
                uint32_t aB3 = cvt_tf32(hi81*hjB1);
                #pragma unroll
                for (int nt=0; nt<8; nt++) {
                    uint32_t b0 = __float_as_uint(sm->wtf[k0][nt*8+g]);
                    uint32_t b1 = __float_as_uint(sm->wtf[k1][nt*8+g]);
                    mma_tf32(accA[nt], aA0, aA1, aA2, aA3, b0, b1);
                    mma_tf32(accB[nt], aB0, aB1, aB2, aB3, b0, b1);
                }
            }

            #pragma unroll
            for (int half=0; half<2; half++) {
                int jj = half ? jjB : jjA;
                float (*acc)[4] = half ? accB : accA;
                float e_g  = ((sm->bm0[ii0+g  ][jj>>5] >> (jj&31)) & 1u) ? 1.f : 0.f;
                float e_g8 = ((sm->bm0[ii0+g+8][jj>>5] >> (jj&31)) & 1u) ? 1.f : 0.f;
                float pre0[16], pre1[16];
                #pragma unroll
                for (int nt=0; nt<8; nt++) {
                    #pragma unroll
                    for (int hf=0; hf<2; hf++) {
                        int i = 2*nt + hf;
                        pre0[i] = acc[nt][hf]   + hb_r[i] + e_g *we_r[i];
                        pre1[i] = acc[nt][2+hf] + hb_r[i] + e_g8*we_r[i];
                    }
                }
                float m0, r0, m1, r1;
                emit(rs, sm->vqa[jj], pre0, pre1, g, tg, m0, r0, m1, r1);

                if (!diag) {
                    float ep_g  = ((sm->bm1[jj][(ii0+g  )>>5] >> ((ii0+g  )&31)) & 1u) ? 1.f : 0.f;
                    float ep_g8 = ((sm->bm1[jj][(ii0+g+8)>>5] >> ((ii0+g+8)&31)) & 1u) ? 1.f : 0.f;
                    float dd0 = ep_g - e_g, dd1 = ep_g8 - e_g8;
                    bool nd = (dd0 != 0.f) || (dd1 != 0.f);
                    if (__any_sync(0xffffffffu, nd)) {
                        emit_delta(sm->st2[w], sm->vqa2[jj], pre0, pre1,
                                   dd0, dd1, m0, r0, m1, r1, we_r, g, tg);
                    }
                }
            }
        }

        // ---- write register row sums to st (once per i0b) ----
        #pragma unroll
        for (int nt=0; nt<8; nt++) {
            int ch0 = nt*8 + 2*tg;
            *reinterpret_cast<float2*>(&sm->st[w][g  ][ch0]) = make_float2(rs[2*nt],    rs[2*nt+1]);
            *reinterpret_cast<float2*>(&sm->st[w][g+8][ch0]) = make_float2(rs[16+2*nt], rs[16+2*nt+1]);
        }

        // ---- block reduce warp-private accumulators (once per ii0 group) ----
        __syncthreads();
        {
            int r = t >> 4, cq = (t & 15) * 4;
            float4 s4 = make_float4(0.f,0.f,0.f,0.f);
            #pragma unroll
            for (int ww=0; ww<8; ww++) {
                float4 v = *reinterpret_cast<float4*>(&sm->st[ww][r][cq]);
                s4.x += v.x; s4.y += v.y; s4.z += v.z; s4.w += v.w;
            }
            float4* d4 = reinterpret_cast<float4*>(&sm->svp[ii0+r][cq]);
            float4 o = *d4;
            o.x += s4.x; o.y += s4.y; o.z += s4.z; o.w += s4.w;
            *d4 = o;
            if (!diag) {
                float4 s5 = make_float4(0.f,0.f,0.f,0.f);
                #pragma unroll
                for (int ww=0; ww<8; ww++) {
                    float4 v = *reinterpret_cast<float4*>(&sm->st2[ww][r][cq]);
                    s5.x += v.x; s5.y += v.y; s5.z += v.z; s5.w += v.w;
                }
                float4* d5 = reinterpret_cast<float4*>(&sm->svq2[ii0+r][cq]);
                float4 o2 = *d5;
                o2.x += s5.x; o2.y += s5.y; o2.z += s5.z; o2.w += s5.w;
                *d5 = o2;
            }
        }
        __syncthreads();
    }

    // ---- flush (vector reductions): mirror = normal + sparse corrections ----
    for (int idx=t; idx<DD*DD/2; idx+=256) {
        int rr = idx>>5, cq = (idx&31)*2;
        float rs0 = sm->svp[rr][cq], rs1 = sm->svp[rr][cq+1];
        float cs0 = sm->vqa[rr][cq], cs1 = sm->vqa[rr][cq+1];
        red2(&d_vecp[(i0+rr)*DD + cq], rs0, rs1);
        red2(&d_vecq[(j0+rr)*DD + cq], cs0, cs1);
        if (!diag) {
            red2(&d_vecq[(i0+rr)*DD + cq], rs0 + sm->svq2[rr][cq], rs1 + sm->svq2[rr][cq+1]);
            red2(&d_vecp[(j0+rr)*DD + cq], cs0 + sm->vqa2[rr][cq], cs1 + sm->vqa2[rr][cq+1]);
        }
    }
}

// ------------------------- phase C ------------------------------------------
__global__ void k_prec(const float* __restrict__ gW) {
    __shared__ float s_v[DD];
    int i = blockIdx.x, c = threadIdx.x;
    int which = blockIdx.y;
    const float* src = which ? d_vecq : d_vecp;
    const float* w   = gW + (which ? 129 : 65)*DD;
    float*       dst = which ? d_VQ : d_VP;
    s_v[c] = src[i*DD + c];
    __syncthreads();
    float acc = 0.f;
    #pragma unroll 8
    for (int k=0; k<DD; k++) acc = fmaf(s_v[k], w[k*DD+c], acc);
    dst[i*DD + c] = acc;
}

__global__ void k_gpairs(const int* __restrict__ pos, const float* __restrict__ gW,
                         const float* __restrict__ gb, const float* __restrict__ lW,
                         const float* __restrict__ lb, float* __restrict__ out) {
    __shared__ float sgw[DD+1][DD];
    __shared__ float sgb[DD], slw[DD];
    int t = threadIdx.x;
    for (int idx=t; idx<(DD+1)*DD; idx+=256) sgw[idx>>6][idx&63] = gW[idx];
    if (t < DD) { sgb[t] = gb[t]; slw[t] = lW[t]; }
    __syncthreads();

    int gt = blockIdx.x*256 + t;
    int p = gt >> 5, lane = gt & 31;
    if (p >= NP) return;
    int i = pos[2*p], j = pos[2*p+1];
    int c0 = lane, c1 = lane + 32;
    const float* hi = d_h + i*DD;
    const float* hj = d_h + j*DD;

    float g0 = 0.f, g1 = 0.f;
    #pragma unroll 8
    for (int k=0; k<DD; k++) {
        float a = hi[k]*hj[k];
        g0 = fmaf(a, sgw[k][c0], g0);
        g1 = fmaf(a, sgw[k][c1], g1);
    }
    unsigned bij = (unsigned)i*NN + (unsigned)j;
    unsigned bji = (unsigned)j*NN + (unsigned)i;
    float eij = ((d_bitmap[bij>>5] >> (bij & 31u)) & 1u) ? 1.f : 0.f;
    float eji = ((d_bitmap[bji>>5] >> (bji & 31u)) & 1u) ? 1.f : 0.f;

    float aA0 = g0 + sgb[c0] + d_VP[i*DD+c0] + d_VQ[j*DD+c0] + eij*sgw[DD][c0];
    float aA1 = g1 + sgb[c1] + d_VP[i*DD+c1] + d_VQ[j*DD+c1] + eij*sgw[DD][c1];
    float aB0 = g0 + sgb[c0] + d_VP[j*DD+c0] + d_VQ[i*DD+c0] + eji*sgw[DD][c0];
    float aB1 = g1 + sgb[c1] + d_VP[j*DD+c1] + d_VQ[i*DD+c1] + eji*sgw[DD][c1];

    float sA = aA0 + aA1, qA = aA0*aA0 + aA1*aA1;
    float sB = aB0 + aB1, qB = aB0*aB0 + aB1*aB1;
    #pragma unroll
    for (int o=16; o>=1; o>>=1) {
        sA += __shfl_xor_sync(0xffffffffu, sA, o);
        qA += __shfl_xor_sync(0xffffffffu, qA, o);
        sB += __shfl_xor_sync(0xffffffffu, sB, o);
        qB += __shfl_xor_sync(0xffffffffu, qB, o);
    }
    float mA = sA*(1.f/DD);
    float rA = rsqrtf(fmaf(-mA, mA, qA*(1.f/DD)) + LNEPS);
    float mB = sB*(1.f/DD);
    float rB = rsqrtf(fmaf(-mB, mB, qB*(1.f/DD)) + LNEPS);
    float GA0 = fmaxf((aA0-mA)*rA, 0.f), GA1 = fmaxf((aA1-mA)*rA, 0.f);
    float GB0 = fmaxf((aB0-mB)*rB, 0.f), GB1 = fmaxf((aB1-mB)*rB, 0.f);

    float o0 = GA0*GB0*slw[c0] + GA1*GB1*slw[c1];
    #pragma unroll
    for (int o=16; o>=1; o>>=1) o0 += __shfl_xor_sync(0xffffffffu, o0, o);
    if (lane == 0) out[p] = o0 + lb[0];
}

// ------------------------- launch -------------------------------------------
extern "C" void kernel_launch(void* const* d_in, const int* in_sizes, int n_in,
                              void* d_out, int out_size) {
    const int*   x   = (const int*)d_in[0];
    const int*   ei  = (const int*)d_in[1];
    const int*   pos = (const int*)d_in[2];
    const float* emb = (const float*)d_in[3];
    const float* sWl = (const float*)d_in[4];
    const float* sbl = (const float*)d_in[5];
    const float* sWr = (const float*)d_in[6];
    const float* hW  = (const float*)d_in[7];
    const float* hb  = (const float*)d_in[8];
    const float* gW  = (const float*)d_in[9];
    const float* gb  = (const float*)d_in[10];
    const float* lW  = (const float*)d_in[11];
    const float* lb  = (const float*)d_in[12];
    float* out = (float*)d_out;

    cudaFuncSetAttribute(k_pair, cudaFuncAttributeMaxDynamicSharedMemorySize,
                         (int)sizeof(PairSmem));

    k_init<<<256, 256>>>(x, emb);
    k_scat0<<<NE*32/256, 256>>>(ei);
    k_sage<<<NN, DD>>>(sWl, sbl, sWr, 0);
    k_scatter<<<NE*32/256, 256>>>(ei);
    k_sage<<<NN, DD>>>(sWl, sbl, sWr, 1);
    k_pair<<<136, 256, sizeof(PairSmem)>>>(hW, hb);
    k_prec<<<dim3(NN,2), DD>>>(gW);
    k_gpairs<<<(NP*32)/256, 256>>>(pos, gW, gb, lW, lb, out);
}